// round 1
// baseline (speedup 1.0000x reference)
#include <cuda_runtime.h>
#include <math.h>

// Problem constants
#define BN 16
#define DDIM 256
#define TT 2048
#define KK 1024
#define NPTS (BN*TT)        // 32768 points
#define NQ (BN*DDIM*TT)     // 8388608 elements in quantized output
#define DELTA 1e-4f         // fp32 argmin safety margin (error bound ~1e-5)

// Device scratch (static allocation — no cudaMalloc anywhere)
__device__ float  g_eT[DDIM*KK];      // embeddings transposed [d][k]
__device__ float  g_c2[KK];           // ||e_k||^2
__device__ int    g_enc[NPTS];        // argmin indices
__device__ int    g_nflag;            // count of ambiguous points
__device__ int    g_flags[NPTS];      // ambiguous point ids
__device__ double g_bsum[8192];       // per-block MSE partial sums

__global__ void k_init() { g_nflag = 0; }

// emb [K, D] row-major -> g_eT [D, K]
__global__ void k_transpose(const float* __restrict__ emb) {
    int i = blockIdx.x * blockDim.x + threadIdx.x;   // i = k*256 + d
    if (i < KK * DDIM) {
        int k = i >> 8;
        int d = i & 255;
        g_eT[d * KK + k] = emb[i];
    }
}

__global__ void k_c2() {
    int k = blockIdx.x * blockDim.x + threadIdx.x;
    if (k < KK) {
        float s = 0.f;
        for (int d = 0; d < DDIM; d++) {
            float v = g_eT[d * KK + k];
            s = fmaf(v, v, s);
        }
        g_c2[k] = s;
    }
}

// Pass A: fp32 GEMM (scores s_k = ||e_k||^2 - 2 x.e_k) with fused argmin,
// tracking best + second-best per point. Tile: 64 points x 64 codes x 16 d.
__global__ __launch_bounds__(256) void k_passA(const float* __restrict__ x) {
    __shared__ float As[16][64];
    __shared__ float Bs[16][64];
    __shared__ float rb[64][17];   // pad 17 to kill bank conflicts
    __shared__ float rs[64][17];
    __shared__ int   ri[64][17];

    const int tid = threadIdx.x;
    const int tx = tid & 15;       // point group (4 points each)
    const int ty = tid >> 4;       // code group  (4 codes each)
    const int n0 = blockIdx.x * 64;
    const int b  = n0 / TT;
    const int t0 = n0 % TT;
    const float* xb = x + (size_t)b * DDIM * TT + t0;

    const int lr = tid >> 4;              // load row (d within chunk)
    const int lc = (tid & 15) << 2;       // load col (float4)

    float best[4] = {1e30f, 1e30f, 1e30f, 1e30f};
    float sec[4]  = {1e30f, 1e30f, 1e30f, 1e30f};
    int   bidx[4] = {0, 0, 0, 0};

    for (int kt = 0; kt < 16; kt++) {
        float acc[4][4];
        #pragma unroll
        for (int i = 0; i < 4; i++)
            #pragma unroll
            for (int j = 0; j < 4; j++) acc[i][j] = 0.f;

        for (int dc = 0; dc < 16; dc++) {
            int d = dc * 16 + lr;
            *(float4*)&As[lr][lc] = *(const float4*)&xb[(size_t)d * TT + lc];
            *(float4*)&Bs[lr][lc] = *(const float4*)&g_eT[d * KK + kt * 64 + lc];
            __syncthreads();
            #pragma unroll
            for (int dd = 0; dd < 16; dd++) {
                float4 a = *(float4*)&As[dd][tx * 4];
                float4 e = *(float4*)&Bs[dd][ty * 4];
                float av[4] = {a.x, a.y, a.z, a.w};
                float ev[4] = {e.x, e.y, e.z, e.w};
                #pragma unroll
                for (int i = 0; i < 4; i++)
                    #pragma unroll
                    for (int j = 0; j < 4; j++)
                        acc[i][j] = fmaf(av[i], ev[j], acc[i][j]);
            }
            __syncthreads();
        }
        #pragma unroll
        for (int j = 0; j < 4; j++) {
            int k = kt * 64 + ty * 4 + j;
            float c2k = __ldg(&g_c2[k]);
            #pragma unroll
            for (int i = 0; i < 4; i++) {
                float s = fmaf(-2.f, acc[i][j], c2k);
                if (s < best[i]) { sec[i] = best[i]; best[i] = s; bidx[i] = k; }
                else if (s < sec[i]) { sec[i] = s; }
            }
        }
    }

    #pragma unroll
    for (int i = 0; i < 4; i++) {
        int pt = tx * 4 + i;
        rb[pt][ty] = best[i];
        rs[pt][ty] = sec[i];
        ri[pt][ty] = bidx[i];
    }
    __syncthreads();

    if (tid < 64) {
        float b0 = rb[tid][0], s0 = rs[tid][0];
        int   i0 = ri[tid][0];
        for (int e = 1; e < 16; e++) {
            float b1 = rb[tid][e], s1 = rs[tid][e];
            int   i1 = ri[tid][e];
            if (b1 < b0) {
                s0 = fminf(fminf(s0, s1), b0);
                b0 = b1; i0 = i1;
            } else {
                s0 = fminf(fminf(s0, s1), b1);
            }
        }
        int n = n0 + tid;
        g_enc[n] = i0;
        if (s0 - b0 < DELTA) {
            int pos = atomicAdd(&g_nflag, 1);
            g_flags[pos] = n;
        }
    }
}

// Pass B: exact fp64 re-resolution for flagged (near-tie) points.
__global__ __launch_bounds__(128) void k_passB(const float* __restrict__ x,
                                               const float* __restrict__ emb) {
    __shared__ float  xs[DDIM];
    __shared__ float  rv[128];
    __shared__ double rdv[128];
    __shared__ int    rk[128];
    const int tid = threadIdx.x;
    const int nf = g_nflag;

    for (int fi = blockIdx.x; fi < nf; fi += gridDim.x) {
        int n = g_flags[fi];
        int b = n / TT, t = n % TT;
        __syncthreads();
        for (int d = tid; d < DDIM; d += 128)
            xs[d] = x[(size_t)b * DDIM * TT + (size_t)d * TT + t];
        __syncthreads();

        // sweep 1: fp32 min score
        float mymin = 1e30f;
        for (int k = tid; k < KK; k += 128) {
            const float4* er = (const float4*)&emb[k * DDIM];
            float dot = 0.f;
            #pragma unroll 4
            for (int d4 = 0; d4 < 64; d4++) {
                float4 e4 = er[d4];
                dot = fmaf(xs[d4 * 4 + 0], e4.x, dot);
                dot = fmaf(xs[d4 * 4 + 1], e4.y, dot);
                dot = fmaf(xs[d4 * 4 + 2], e4.z, dot);
                dot = fmaf(xs[d4 * 4 + 3], e4.w, dot);
            }
            float s = fmaf(-2.f, dot, g_c2[k]);
            mymin = fminf(mymin, s);
        }
        rv[tid] = mymin;
        __syncthreads();
        for (int off = 64; off > 0; off >>= 1) {
            if (tid < off) rv[tid] = fminf(rv[tid], rv[tid + off]);
            __syncthreads();
        }
        float thresh = rv[0] + 2e-4f;

        // sweep 2: candidates -> exact fp64 distance, lowest index wins ties
        double bd = 1e300;
        int    bk = KK;
        for (int k = tid; k < KK; k += 128) {
            const float4* er = (const float4*)&emb[k * DDIM];
            float dot = 0.f;
            #pragma unroll 4
            for (int d4 = 0; d4 < 64; d4++) {
                float4 e4 = er[d4];
                dot = fmaf(xs[d4 * 4 + 0], e4.x, dot);
                dot = fmaf(xs[d4 * 4 + 1], e4.y, dot);
                dot = fmaf(xs[d4 * 4 + 2], e4.z, dot);
                dot = fmaf(xs[d4 * 4 + 3], e4.w, dot);
            }
            float s = fmaf(-2.f, dot, g_c2[k]);
            if (s <= thresh) {
                double d2 = 0.0;
                for (int d = 0; d < DDIM; d++) {
                    double diff = (double)xs[d] - (double)emb[k * DDIM + d];
                    d2 = fma(diff, diff, d2);
                }
                if (d2 < bd || (d2 == bd && k < bk)) { bd = d2; bk = k; }
            }
        }
        rdv[tid] = bd; rk[tid] = bk;
        __syncthreads();
        for (int off = 64; off > 0; off >>= 1) {
            if (tid < off) {
                double od = rdv[tid + off];
                int    ok = rk[tid + off];
                if (od < rdv[tid] || (od == rdv[tid] && ok < rk[tid])) {
                    rdv[tid] = od; rk[tid] = ok;
                }
            }
            __syncthreads();
        }
        if (tid == 0) g_enc[n] = rk[0];
    }
}

// Elementwise: quantized_st = x + (q - x), accumulate (q - x)^2 per block.
__global__ __launch_bounds__(256) void k_quant(const float* __restrict__ x,
                                               const float* __restrict__ emb,
                                               float* __restrict__ out,
                                               int do_store) {
    __shared__ double sd[256];
    const int tid = threadIdx.x;
    const int gi = blockIdx.x * 256 + tid;
    const size_t base = (size_t)gi * 4;

    int t = (int)(base % TT);
    size_t tmp = base / TT;
    int d = (int)(tmp % DDIM);
    int b = (int)(tmp / DDIM);

    float4 xv = *(const float4*)&x[base];
    int nb = b * TT + t;
    int i0 = g_enc[nb + 0];
    int i1 = g_enc[nb + 1];
    int i2 = g_enc[nb + 2];
    int i3 = g_enc[nb + 3];
    float q0 = __ldg(&emb[i0 * DDIM + d]);
    float q1 = __ldg(&emb[i1 * DDIM + d]);
    float q2 = __ldg(&emb[i2 * DDIM + d]);
    float q3 = __ldg(&emb[i3 * DDIM + d]);
    float d0 = q0 - xv.x;
    float d1 = q1 - xv.y;
    float d2 = q2 - xv.z;
    float d3 = q3 - xv.w;
    if (do_store) {
        float4 ov = make_float4(xv.x + d0, xv.y + d1, xv.z + d2, xv.w + d3);
        *(float4*)&out[base] = ov;
    }
    double loc = (double)d0 * d0 + (double)d1 * d1 + (double)d2 * d2 + (double)d3 * d3;

    sd[tid] = loc;
    __syncthreads();
    for (int off = 128; off > 0; off >>= 1) {
        if (tid < off) sd[tid] += sd[tid + off];
        __syncthreads();
    }
    if (tid == 0) g_bsum[blockIdx.x] = sd[0];
}

// Deterministic final reduce + scalar outputs.
__global__ void k_scalars(float* __restrict__ out, int out_size) {
    __shared__ double sd[256];
    const int tid = threadIdx.x;
    double loc = 0.0;
    for (int i = tid; i < 8192; i += 256) loc += g_bsum[i];
    sd[tid] = loc;
    __syncthreads();
    for (int off = 128; off > 0; off >>= 1) {
        if (tid < off) sd[tid] += sd[tid + off];
        __syncthreads();
    }
    if (tid == 0 && out_size >= NQ + 3) {
        float mse = (float)(sd[0] / (double)NQ);
        out[NQ + 0] = mse + 0.25f * mse;  // loss (matches ref op order)
        out[NQ + 1] = mse;                // e_latent_loss
        out[NQ + 2] = mse;                // q_latent_loss
    }
}

__global__ void k_indices(float* __restrict__ out, int out_size) {
    int i = blockIdx.x * blockDim.x + threadIdx.x;
    if (i < NPTS && out_size >= NQ + 3 + NPTS)
        out[NQ + 3 + i] = (float)g_enc[i];
}

extern "C" void kernel_launch(void* const* d_in, const int* in_sizes, int n_in,
                              void* d_out, int out_size) {
    const float* x   = (const float*)d_in[0];
    const float* emb = (const float*)d_in[1];
    // Defensive: identify by size in case of ordering surprises.
    if (n_in >= 2 && in_sizes[0] == KK * DDIM && in_sizes[1] == NQ) {
        const float* tmp = x; x = emb; emb = tmp;
    }
    float* out = (float*)d_out;
    int do_store = (out_size >= NQ) ? 1 : 0;

    k_init<<<1, 1>>>();
    k_transpose<<<(KK * DDIM) / 256, 256>>>(emb);
    k_c2<<<KK / 256, 256>>>();
    k_passA<<<NPTS / 64, 256>>>(x);
    k_passB<<<64, 128>>>(x, emb);
    k_quant<<<NQ / (256 * 4), 256>>>(x, emb, out, do_store);
    k_scalars<<<1, 256>>>(out, out_size);
    k_indices<<<NPTS / 256, 256>>>(out, out_size);
}

// round 2
// speedup vs baseline: 1.8363x; 1.8363x over previous
#include <cuda_runtime.h>
#include <math.h>

// Problem constants
#define BN 16
#define DDIM 256
#define TT 2048
#define KK 1024
#define NPTS (BN*TT)        // 32768 points
#define NQ (BN*DDIM*TT)     // 8388608 elements in quantized output
#define DELTA 1e-4f         // fp32 argmin safety margin (error bound ~1e-5)

// Device scratch (static allocation — no cudaMalloc anywhere)
__device__ float  g_eT[DDIM*KK];      // embeddings transposed [d][k]
__device__ float  g_c2[KK];           // ||e_k||^2
__device__ int    g_enc[NPTS];        // argmin indices
__device__ int    g_nflag;            // count of ambiguous points
__device__ int    g_flags[NPTS];      // ambiguous point ids
__device__ double g_bsum[8192];       // per-block MSE partial sums

__global__ void k_init() { g_nflag = 0; }

// emb [K, D] row-major -> g_eT [D, K]
__global__ void k_transpose(const float* __restrict__ emb) {
    int i = blockIdx.x * blockDim.x + threadIdx.x;   // i = k*256 + d
    if (i < KK * DDIM) {
        int k = i >> 8;
        int d = i & 255;
        g_eT[d * KK + k] = emb[i];
    }
}

__global__ void k_c2() {
    int k = blockIdx.x * blockDim.x + threadIdx.x;
    if (k < KK) {
        float s = 0.f;
        for (int d = 0; d < DDIM; d++) {
            float v = g_eT[d * KK + k];
            s = fmaf(v, v, s);
        }
        g_c2[k] = s;
    }
}

// Pass A: fp32 GEMM (scores s_k = ||e_k||^2 - 2 x.e_k) with fused argmin,
// tracking best + second-best per point. Tile: 64 points x 64 codes x 16 d.
__global__ __launch_bounds__(256) void k_passA(const float* __restrict__ x) {
    __shared__ float As[16][64];
    __shared__ float Bs[16][64];
    __shared__ float rb[64][17];   // pad 17 to kill bank conflicts
    __shared__ float rs[64][17];
    __shared__ int   ri[64][17];

    const int tid = threadIdx.x;
    const int tx = tid & 15;       // point group (4 points each)
    const int ty = tid >> 4;       // code group  (4 codes each)
    const int n0 = blockIdx.x * 64;
    const int b  = n0 / TT;
    const int t0 = n0 % TT;
    const float* xb = x + (size_t)b * DDIM * TT + t0;

    const int lr = tid >> 4;              // load row (d within chunk)
    const int lc = (tid & 15) << 2;       // load col (float4)

    float best[4] = {1e30f, 1e30f, 1e30f, 1e30f};
    float sec[4]  = {1e30f, 1e30f, 1e30f, 1e30f};
    int   bidx[4] = {0, 0, 0, 0};

    for (int kt = 0; kt < 16; kt++) {
        float acc[4][4];
        #pragma unroll
        for (int i = 0; i < 4; i++)
            #pragma unroll
            for (int j = 0; j < 4; j++) acc[i][j] = 0.f;

        for (int dc = 0; dc < 16; dc++) {
            int d = dc * 16 + lr;
            *(float4*)&As[lr][lc] = *(const float4*)&xb[(size_t)d * TT + lc];
            *(float4*)&Bs[lr][lc] = *(const float4*)&g_eT[d * KK + kt * 64 + lc];
            __syncthreads();
            #pragma unroll
            for (int dd = 0; dd < 16; dd++) {
                float4 a = *(float4*)&As[dd][tx * 4];
                float4 e = *(float4*)&Bs[dd][ty * 4];
                float av[4] = {a.x, a.y, a.z, a.w};
                float ev[4] = {e.x, e.y, e.z, e.w};
                #pragma unroll
                for (int i = 0; i < 4; i++)
                    #pragma unroll
                    for (int j = 0; j < 4; j++)
                        acc[i][j] = fmaf(av[i], ev[j], acc[i][j]);
            }
            __syncthreads();
        }
        #pragma unroll
        for (int j = 0; j < 4; j++) {
            int k = kt * 64 + ty * 4 + j;
            float c2k = __ldg(&g_c2[k]);
            #pragma unroll
            for (int i = 0; i < 4; i++) {
                float s = fmaf(-2.f, acc[i][j], c2k);
                if (s < best[i]) { sec[i] = best[i]; best[i] = s; bidx[i] = k; }
                else if (s < sec[i]) { sec[i] = s; }
            }
        }
    }

    #pragma unroll
    for (int i = 0; i < 4; i++) {
        int pt = tx * 4 + i;
        rb[pt][ty] = best[i];
        rs[pt][ty] = sec[i];
        ri[pt][ty] = bidx[i];
    }
    __syncthreads();

    if (tid < 64) {
        float b0 = rb[tid][0], s0 = rs[tid][0];
        int   i0 = ri[tid][0];
        for (int e = 1; e < 16; e++) {
            float b1 = rb[tid][e], s1 = rs[tid][e];
            int   i1 = ri[tid][e];
            if (b1 < b0) {
                s0 = fminf(fminf(s0, s1), b0);
                b0 = b1; i0 = i1;
            } else {
                s0 = fminf(fminf(s0, s1), b1);
            }
        }
        int n = n0 + tid;
        g_enc[n] = i0;
        if (s0 - b0 < DELTA) {
            int pos = atomicAdd(&g_nflag, 1);
            g_flags[pos] = n;
        }
    }
}

// Pass B: exact fp64 re-resolution for flagged (near-tie) points.
__global__ __launch_bounds__(128) void k_passB(const float* __restrict__ x,
                                               const float* __restrict__ emb) {
    __shared__ float  xs[DDIM];
    __shared__ float  rv[128];
    __shared__ double rdv[128];
    __shared__ int    rk[128];
    const int tid = threadIdx.x;
    const int nf = g_nflag;

    for (int fi = blockIdx.x; fi < nf; fi += gridDim.x) {
        int n = g_flags[fi];
        int b = n / TT, t = n % TT;
        __syncthreads();
        for (int d = tid; d < DDIM; d += 128)
            xs[d] = x[(size_t)b * DDIM * TT + (size_t)d * TT + t];
        __syncthreads();

        // sweep 1: fp32 min score
        float mymin = 1e30f;
        for (int k = tid; k < KK; k += 128) {
            const float4* er = (const float4*)&emb[k * DDIM];
            float dot = 0.f;
            #pragma unroll 4
            for (int d4 = 0; d4 < 64; d4++) {
                float4 e4 = er[d4];
                dot = fmaf(xs[d4 * 4 + 0], e4.x, dot);
                dot = fmaf(xs[d4 * 4 + 1], e4.y, dot);
                dot = fmaf(xs[d4 * 4 + 2], e4.z, dot);
                dot = fmaf(xs[d4 * 4 + 3], e4.w, dot);
            }
            float s = fmaf(-2.f, dot, g_c2[k]);
            mymin = fminf(mymin, s);
        }
        rv[tid] = mymin;
        __syncthreads();
        for (int off = 64; off > 0; off >>= 1) {
            if (tid < off) rv[tid] = fminf(rv[tid], rv[tid + off]);
            __syncthreads();
        }
        float thresh = rv[0] + 2e-4f;

        // sweep 2: candidates -> exact fp64 distance, lowest index wins ties
        double bd = 1e300;
        int    bk = KK;
        for (int k = tid; k < KK; k += 128) {
            const float4* er = (const float4*)&emb[k * DDIM];
            float dot = 0.f;
            #pragma unroll 4
            for (int d4 = 0; d4 < 64; d4++) {
                float4 e4 = er[d4];
                dot = fmaf(xs[d4 * 4 + 0], e4.x, dot);
                dot = fmaf(xs[d4 * 4 + 1], e4.y, dot);
                dot = fmaf(xs[d4 * 4 + 2], e4.z, dot);
                dot = fmaf(xs[d4 * 4 + 3], e4.w, dot);
            }
            float s = fmaf(-2.f, dot, g_c2[k]);
            if (s <= thresh) {
                double d2 = 0.0;
                for (int d = 0; d < DDIM; d++) {
                    double diff = (double)xs[d] - (double)emb[k * DDIM + d];
                    d2 = fma(diff, diff, d2);
                }
                if (d2 < bd || (d2 == bd && k < bk)) { bd = d2; bk = k; }
            }
        }
        rdv[tid] = bd; rk[tid] = bk;
        __syncthreads();
        for (int off = 64; off > 0; off >>= 1) {
            if (tid < off) {
                double od = rdv[tid + off];
                int    ok = rk[tid + off];
                if (od < rdv[tid] || (od == rdv[tid] && ok < rk[tid])) {
                    rdv[tid] = od; rk[tid] = ok;
                }
            }
            __syncthreads();
        }
        if (tid == 0) g_enc[n] = rk[0];
    }
}

// Elementwise: quantized_st = x + (q - x), accumulate (q - x)^2 per block.
// fp32 accumulation (per-block sums ~1e3 -> fp32 tree error ~1e-7 relative);
// one double conversion per block. Avoids B300's ~8 DFMA/cyc chip-wide fp64 wall.
__global__ __launch_bounds__(256) void k_quant(const float* __restrict__ x,
                                               const float* __restrict__ emb,
                                               float* __restrict__ out,
                                               int do_store) {
    __shared__ float sf[256];
    const int tid = threadIdx.x;
    const int gi = blockIdx.x * 256 + tid;
    const size_t base = (size_t)gi * 4;

    int t = (int)(base % TT);
    size_t tmp = base / TT;
    int d = (int)(tmp % DDIM);
    int b = (int)(tmp / DDIM);

    float4 xv = *(const float4*)&x[base];
    int nb = b * TT + t;
    int i0 = g_enc[nb + 0];
    int i1 = g_enc[nb + 1];
    int i2 = g_enc[nb + 2];
    int i3 = g_enc[nb + 3];
    float q0 = __ldg(&emb[i0 * DDIM + d]);
    float q1 = __ldg(&emb[i1 * DDIM + d]);
    float q2 = __ldg(&emb[i2 * DDIM + d]);
    float q3 = __ldg(&emb[i3 * DDIM + d]);
    float d0 = q0 - xv.x;
    float d1 = q1 - xv.y;
    float d2 = q2 - xv.z;
    float d3 = q3 - xv.w;
    if (do_store) {
        float4 ov = make_float4(xv.x + d0, xv.y + d1, xv.z + d2, xv.w + d3);
        *(float4*)&out[base] = ov;
    }
    float loc = d0 * d0;
    loc = fmaf(d1, d1, loc);
    loc = fmaf(d2, d2, loc);
    loc = fmaf(d3, d3, loc);

    sf[tid] = loc;
    __syncthreads();
    for (int off = 128; off > 0; off >>= 1) {
        if (tid < off) sf[tid] += sf[tid + off];
        __syncthreads();
    }
    if (tid == 0) g_bsum[blockIdx.x] = (double)sf[0];
}

// Deterministic final reduce + scalar outputs.
__global__ void k_scalars(float* __restrict__ out, int out_size) {
    __shared__ double sd[256];
    const int tid = threadIdx.x;
    double loc = 0.0;
    for (int i = tid; i < 8192; i += 256) loc += g_bsum[i];
    sd[tid] = loc;
    __syncthreads();
    for (int off = 128; off > 0; off >>= 1) {
        if (tid < off) sd[tid] += sd[tid + off];
        __syncthreads();
    }
    if (tid == 0 && out_size >= NQ + 3) {
        float mse = (float)(sd[0] / (double)NQ);
        out[NQ + 0] = mse + 0.25f * mse;  // loss (matches ref op order)
        out[NQ + 1] = mse;                // e_latent_loss
        out[NQ + 2] = mse;                // q_latent_loss
    }
}

__global__ void k_indices(float* __restrict__ out, int out_size) {
    int i = blockIdx.x * blockDim.x + threadIdx.x;
    if (i < NPTS && out_size >= NQ + 3 + NPTS)
        out[NQ + 3 + i] = (float)g_enc[i];
}

extern "C" void kernel_launch(void* const* d_in, const int* in_sizes, int n_in,
                              void* d_out, int out_size) {
    const float* x   = (const float*)d_in[0];
    const float* emb = (const float*)d_in[1];
    // Defensive: identify by size in case of ordering surprises.
    if (n_in >= 2 && in_sizes[0] == KK * DDIM && in_sizes[1] == NQ) {
        const float* tmp = x; x = emb; emb = tmp;
    }
    float* out = (float*)d_out;
    int do_store = (out_size >= NQ) ? 1 : 0;

    k_init<<<1, 1>>>();
    k_transpose<<<(KK * DDIM) / 256, 256>>>(emb);
    k_c2<<<KK / 256, 256>>>();
    k_passA<<<NPTS / 64, 256>>>(x);
    k_passB<<<256, 128>>>(x, emb);
    k_quant<<<NQ / (256 * 4), 256>>>(x, emb, out, do_store);
    k_scalars<<<1, 256>>>(out, out_size);
    k_indices<<<NPTS / 256, 256>>>(out, out_size);
}

// round 4
// speedup vs baseline: 5.3474x; 2.9120x over previous
#include <cuda_runtime.h>
#include <cuda_bf16.h>
#include <math.h>
#include <stdint.h>

// Problem constants
#define BN 16
#define DDIM 256
#define TT 2048
#define KK 1024
#define NPTS (BN*TT)        // 32768 points
#define NQ (BN*DDIM*TT)     // 8388608 elements
#define DELTA_TC 1e-5f      // bf16 3-term split score error ~1e-7; 100x margin

// ---------------- Device scratch ----------------
__device__ __nv_bfloat16 g_xhi[(size_t)NPTS * DDIM];
__device__ __nv_bfloat16 g_xlo[(size_t)NPTS * DDIM];
__device__ __nv_bfloat16 g_ehi[KK * DDIM];
__device__ __nv_bfloat16 g_elo[KK * DDIM];
__device__ float  g_c2[KK];
__device__ float  g_best[NPTS];
__device__ int    g_enc[NPTS];
__device__ int    g_nflag;
__device__ int    g_flags[NPTS];
__device__ double g_bsum[8192];

__global__ void k_init() { g_nflag = 0; }

// ---------------- baseline-PTX helpers ----------------
__device__ __forceinline__ uint32_t smem_u32(const void* p) {
    uint32_t a;
    asm("{ .reg .u64 t; cvta.to.shared.u64 t, %1; cvt.u32.u64 %0, t; }" : "=r"(a) : "l"(p));
    return a;
}
__device__ __forceinline__ void cpasync16(uint32_t dst, const void* src) {
    asm volatile("cp.async.cg.shared.global [%0], [%1], 16;"
                 :: "r"(dst), "l"(__cvta_generic_to_global(src)) : "memory");
}
#define CP_COMMIT() asm volatile("cp.async.commit_group;" ::: "memory")
#define CP_WAIT0()  asm volatile("cp.async.wait_group 0;" ::: "memory")

__device__ __forceinline__ void ldm_x4(uint32_t a, uint32_t& r0, uint32_t& r1,
                                       uint32_t& r2, uint32_t& r3) {
    asm volatile("ldmatrix.sync.aligned.m8n8.x4.shared.b16 {%0,%1,%2,%3}, [%4];"
                 : "=r"(r0), "=r"(r1), "=r"(r2), "=r"(r3) : "r"(a));
}
__device__ __forceinline__ void ldm_x2(uint32_t a, uint32_t& r0, uint32_t& r1) {
    asm volatile("ldmatrix.sync.aligned.m8n8.x2.shared.b16 {%0,%1}, [%2];"
                 : "=r"(r0), "=r"(r1) : "r"(a));
}
__device__ __forceinline__ void mma_bf16(float* d, const uint32_t* a,
                                         uint32_t b0, uint32_t b1) {
    asm volatile("mma.sync.aligned.m16n8k16.row.col.f32.bf16.bf16.f32 "
                 "{%0,%1,%2,%3}, {%4,%5,%6,%7}, {%8,%9}, {%0,%1,%2,%3};"
                 : "+f"(d[0]), "+f"(d[1]), "+f"(d[2]), "+f"(d[3])
                 : "r"(a[0]), "r"(a[1]), "r"(a[2]), "r"(a[3]), "r"(b0), "r"(b1));
}

// ---------------- prep: bf16 hi/lo splits + ||e||^2 ----------------
__global__ __launch_bounds__(256) void k_prep_e(const float* __restrict__ emb) {
    __shared__ float red[256];
    int k = blockIdx.x, d = threadIdx.x;
    float v = emb[k * DDIM + d];
    __nv_bfloat16 hi = __float2bfloat16(v);
    float hf = __bfloat162float(hi);
    __nv_bfloat16 lo = __float2bfloat16(v - hf);
    g_ehi[k * DDIM + d] = hi;
    g_elo[k * DDIM + d] = lo;
    red[d] = v * v;
    __syncthreads();
    for (int off = 128; off > 0; off >>= 1) {
        if (d < off) red[d] += red[d + off];
        __syncthreads();
    }
    if (d == 0) g_c2[k] = red[0];
}

__global__ __launch_bounds__(256) void k_prep_x(const float* __restrict__ x) {
    __shared__ float tile[32][33];
    int t0 = blockIdx.x * 32, d0 = blockIdx.y * 32, b = blockIdx.z;
    int tx = threadIdx.x, ty = threadIdx.y;
    #pragma unroll
    for (int j = 0; j < 4; j++) {
        int r = ty + j * 8;
        tile[r][tx] = x[((size_t)(b * DDIM + d0 + r)) * TT + t0 + tx];
    }
    __syncthreads();
    #pragma unroll
    for (int j = 0; j < 4; j++) {
        int r = ty + j * 8;
        size_t n = (size_t)b * TT + t0 + r;
        float v = tile[tx][r];
        __nv_bfloat16 hi = __float2bfloat16(v);
        float hf = __bfloat162float(hi);
        __nv_bfloat16 lo = __float2bfloat16(v - hf);
        g_xhi[n * DDIM + d0 + tx] = hi;
        g_xlo[n * DDIM + d0 + tx] = lo;
    }
}

// ---------------- Pass A: mma.sync bf16 3-term GEMM + fused argmin ----------------
// CTA: 128 points x 1024 codes (8 phases of 128). K chunks of 32 dims,
// double-buffered cp.async. smem matrix: 128 rows x 32 b16 padded to 40 (80 B row).
#define ROWB 80                  // bytes per smem row
#define MATB (128 * ROWB)        // 10240 B per matrix chunk
#define BUFB (4 * MATB)          // Ahi,Alo,Bhi,Blo
#define C2OFF (2 * BUFB)         // 81920
#define GEMM_DSMEM (C2OFF + KK * 4)

__device__ __forceinline__ void issue_chunk(int q, uint32_t base, int tid, int m0) {
    int ph = q >> 3, kc = q & 7;
    const __nv_bfloat16* xh = g_xhi + (size_t)m0 * DDIM;
    const __nv_bfloat16* xl = g_xlo + (size_t)m0 * DDIM;
    const __nv_bfloat16* eh = g_ehi + (size_t)(ph * 128) * DDIM;
    const __nv_bfloat16* el = g_elo + (size_t)(ph * 128) * DDIM;
    #pragma unroll
    for (int it = 0; it < 2; it++) {
        int idx = tid + it * 256;          // 0..511
        int row = idx >> 2, c16 = idx & 3;
        int gof = row * DDIM + kc * 32 + c16 * 8;
        uint32_t so = (uint32_t)(row * ROWB + c16 * 16);
        cpasync16(base + 0 * MATB + so, xh + gof);
        cpasync16(base + 1 * MATB + so, xl + gof);
        cpasync16(base + 2 * MATB + so, eh + gof);
        cpasync16(base + 3 * MATB + so, el + gof);
    }
}

__global__ void __launch_bounds__(256, 2) k_gemm() {
    extern __shared__ char dsm[];
    __shared__ float s_mb[2][128];
    __shared__ float s_ms[2][128];
    __shared__ int   s_mi[2][128];

    const uint32_t smb = smem_u32(dsm);
    float* c2s = (float*)(dsm + C2OFF);

    const int tid = threadIdx.x;
    const int wid = tid >> 5;
    const int lane = tid & 31;
    const int wm = wid >> 1;       // 0..3 (M)
    const int wn = wid & 1;        // 0..1 (N)
    const int m0 = blockIdx.x * 128;

    for (int i = tid; i < KK; i += 256) c2s[i] = g_c2[i];

    // ldmatrix per-thread address components
    const int a_row = lane & 15;
    const int a_c8  = (lane >> 4) * 8;       // b16 units
    const int b_row = lane & 7;
    const int b_c8  = ((lane >> 3) & 1) * 8;

    float best[4] = {1e30f, 1e30f, 1e30f, 1e30f};
    float sec[4]  = {1e30f, 1e30f, 1e30f, 1e30f};
    int   bidx[4] = {0, 0, 0, 0};

    issue_chunk(0, smb, tid, m0);
    CP_COMMIT();
    int buf = 0;

    for (int ph = 0; ph < 8; ph++) {
        float acc[2][8][4];
        #pragma unroll
        for (int mt = 0; mt < 2; mt++)
            #pragma unroll
            for (int nt = 0; nt < 8; nt++)
                #pragma unroll
                for (int r = 0; r < 4; r++) acc[mt][nt][r] = 0.f;

        for (int kc = 0; kc < 8; kc++) {
            CP_WAIT0();
            __syncthreads();
            int q = ph * 8 + kc;
            if (q < 63) {
                issue_chunk(q + 1, smb + (uint32_t)((buf ^ 1) * BUFB), tid, m0);
                CP_COMMIT();
            }

            const uint32_t ab  = smb + (uint32_t)(buf * BUFB);
            const uint32_t alb = ab + MATB;
            const uint32_t bb  = ab + 2 * MATB;
            const uint32_t blb = ab + 3 * MATB;

            #pragma unroll
            for (int ks = 0; ks < 2; ks++) {
                const int kb = ks * 16;
                uint32_t ao0 = (uint32_t)((wm * 32 + a_row) * ROWB + (kb + a_c8) * 2);
                uint32_t ao1 = (uint32_t)((wm * 32 + 16 + a_row) * ROWB + (kb + a_c8) * 2);
                uint32_t ah0[4], ah1[4], al0[4], al1[4];
                ldm_x4(ab + ao0,  ah0[0], ah0[1], ah0[2], ah0[3]);
                ldm_x4(ab + ao1,  ah1[0], ah1[1], ah1[2], ah1[3]);
                ldm_x4(alb + ao0, al0[0], al0[1], al0[2], al0[3]);
                ldm_x4(alb + ao1, al1[0], al1[1], al1[2], al1[3]);
                #pragma unroll
                for (int nt = 0; nt < 8; nt++) {
                    uint32_t bo = (uint32_t)((wn * 64 + nt * 8 + b_row) * ROWB + (kb + b_c8) * 2);
                    uint32_t bh0, bh1, bl0, bl1;
                    ldm_x2(bb + bo,  bh0, bh1);
                    ldm_x2(blb + bo, bl0, bl1);
                    mma_bf16(acc[0][nt], ah0, bh0, bh1);
                    mma_bf16(acc[1][nt], ah1, bh0, bh1);
                    mma_bf16(acc[0][nt], al0, bh0, bh1);
                    mma_bf16(acc[1][nt], al1, bh0, bh1);
                    mma_bf16(acc[0][nt], ah0, bl0, bl1);
                    mma_bf16(acc[1][nt], ah1, bl0, bl1);
                }
            }
            __syncthreads();
            buf ^= 1;
        }

        // epilogue: scores + argmin update (rows: wm*32 + mt*16 + h*8 + lane/4)
        #pragma unroll
        for (int mt = 0; mt < 2; mt++) {
            #pragma unroll
            for (int h = 0; h < 2; h++) {
                const int slot = mt * 2 + h;
                #pragma unroll
                for (int nt = 0; nt < 8; nt++) {
                    int k0 = ph * 128 + wn * 64 + nt * 8 + (lane & 3) * 2;
                    float s0 = fmaf(-2.f, acc[mt][nt][2 * h + 0], c2s[k0]);
                    float s1 = fmaf(-2.f, acc[mt][nt][2 * h + 1], c2s[k0 + 1]);
                    if (s0 < best[slot]) { sec[slot] = best[slot]; best[slot] = s0; bidx[slot] = k0; }
                    else if (s0 < sec[slot]) sec[slot] = s0;
                    if (s1 < best[slot]) { sec[slot] = best[slot]; best[slot] = s1; bidx[slot] = k0 + 1; }
                    else if (s1 < sec[slot]) sec[slot] = s1;
                }
            }
        }
    }

    // merge: quad shfl (4 lanes share a row), then the 2 N-warps via smem
    #pragma unroll
    for (int slot = 0; slot < 4; slot++) {
        float b = best[slot], s = sec[slot];
        int i = bidx[slot];
        #pragma unroll
        for (int off = 1; off <= 2; off <<= 1) {
            float ob = __shfl_xor_sync(0xffffffffu, b, off);
            float os = __shfl_xor_sync(0xffffffffu, s, off);
            int   oi = __shfl_xor_sync(0xffffffffu, i, off);
            if (ob < b) { s = fminf(os, b); b = ob; i = oi; }
            else { s = fminf(s, ob); if (ob == b && oi < i) i = oi; }
        }
        if ((lane & 3) == 0) {
            int mt = slot >> 1, h = slot & 1;
            int row = wm * 32 + mt * 16 + h * 8 + (lane >> 2);
            s_mb[wn][row] = b; s_ms[wn][row] = s; s_mi[wn][row] = i;
        }
    }
    __syncthreads();
    if (tid < 128) {
        float b0 = s_mb[0][tid], s0 = s_ms[0][tid];
        int i0 = s_mi[0][tid];
        float b1 = s_mb[1][tid], s1 = s_ms[1][tid];
        int i1 = s_mi[1][tid];
        float b, s; int i;
        if (b1 < b0) { b = b1; i = i1; s = fminf(s1, b0); }
        else { b = b0; i = (b1 == b0 && i1 < i0) ? i1 : i0; s = fminf(s0, b1); }
        int n = m0 + tid;
        g_enc[n] = i;
        g_best[n] = b;
        if (s - b < DELTA_TC) {
            int pos = atomicAdd(&g_nflag, 1);
            g_flags[pos] = n;
        }
    }
}

// ---------------- Pass B: exact fp64 re-resolution for near-ties ----------------
__global__ __launch_bounds__(128) void k_passB(const float* __restrict__ x,
                                               const float* __restrict__ emb) {
    __shared__ float  xs[DDIM];
    __shared__ double rdv[128];
    __shared__ int    rk[128];
    const int tid = threadIdx.x;
    const int nf = g_nflag;

    for (int fi = blockIdx.x; fi < nf; fi += gridDim.x) {
        int n = g_flags[fi];
        int b = n / TT, t = n % TT;
        __syncthreads();
        for (int d = tid; d < DDIM; d += 128)
            xs[d] = x[(size_t)b * DDIM * TT + (size_t)d * TT + t];
        __syncthreads();

        float thresh = g_best[n] + 2e-4f;
        double bd = 1e300;
        int    bk = KK;
        for (int k = tid; k < KK; k += 128) {
            const float4* er = (const float4*)&emb[k * DDIM];
            float dot = 0.f;
            #pragma unroll 4
            for (int d4 = 0; d4 < 64; d4++) {
                float4 e4 = er[d4];
                dot = fmaf(xs[d4 * 4 + 0], e4.x, dot);
                dot = fmaf(xs[d4 * 4 + 1], e4.y, dot);
                dot = fmaf(xs[d4 * 4 + 2], e4.z, dot);
                dot = fmaf(xs[d4 * 4 + 3], e4.w, dot);
            }
            float s = fmaf(-2.f, dot, g_c2[k]);
            if (s <= thresh) {
                double d2 = 0.0;
                for (int d = 0; d < DDIM; d++) {
                    double diff = (double)xs[d] - (double)emb[k * DDIM + d];
                    d2 = fma(diff, diff, d2);
                }
                if (d2 < bd || (d2 == bd && k < bk)) { bd = d2; bk = k; }
            }
        }
        rdv[tid] = bd; rk[tid] = bk;
        __syncthreads();
        for (int off = 64; off > 0; off >>= 1) {
            if (tid < off) {
                double od = rdv[tid + off];
                int    ok = rk[tid + off];
                if (od < rdv[tid] || (od == rdv[tid] && ok < rk[tid])) {
                    rdv[tid] = od; rk[tid] = ok;
                }
            }
            __syncthreads();
        }
        if (tid == 0) g_enc[n] = rk[0];
    }
}

// ---------------- quantized_st + MSE partials ----------------
__global__ __launch_bounds__(256) void k_quant(const float* __restrict__ x,
                                               const float* __restrict__ emb,
                                               float* __restrict__ out,
                                               int do_store) {
    __shared__ float sf[256];
    const int tid = threadIdx.x;
    const int gi = blockIdx.x * 256 + tid;
    const size_t base = (size_t)gi * 4;

    int t = (int)(base % TT);
    size_t tmp = base / TT;
    int d = (int)(tmp % DDIM);
    int b = (int)(tmp / DDIM);

    float4 xv = *(const float4*)&x[base];
    int nb = b * TT + t;
    int i0 = g_enc[nb + 0];
    int i1 = g_enc[nb + 1];
    int i2 = g_enc[nb + 2];
    int i3 = g_enc[nb + 3];
    float q0 = __ldg(&emb[i0 * DDIM + d]);
    float q1 = __ldg(&emb[i1 * DDIM + d]);
    float q2 = __ldg(&emb[i2 * DDIM + d]);
    float q3 = __ldg(&emb[i3 * DDIM + d]);
    float d0 = q0 - xv.x;
    float d1 = q1 - xv.y;
    float d2 = q2 - xv.z;
    float d3 = q3 - xv.w;
    if (do_store) {
        float4 ov = make_float4(xv.x + d0, xv.y + d1, xv.z + d2, xv.w + d3);
        *(float4*)&out[base] = ov;
    }
    float loc = d0 * d0;
    loc = fmaf(d1, d1, loc);
    loc = fmaf(d2, d2, loc);
    loc = fmaf(d3, d3, loc);

    sf[tid] = loc;
    __syncthreads();
    for (int off = 128; off > 0; off >>= 1) {
        if (tid < off) sf[tid] += sf[tid + off];
        __syncthreads();
    }
    if (tid == 0) g_bsum[blockIdx.x] = (double)sf[0];
}

__global__ void k_scalars(float* __restrict__ out, int out_size) {
    __shared__ double sd[256];
    const int tid = threadIdx.x;
    double loc = 0.0;
    for (int i = tid; i < 8192; i += 256) loc += g_bsum[i];
    sd[tid] = loc;
    __syncthreads();
    for (int off = 128; off > 0; off >>= 1) {
        if (tid < off) sd[tid] += sd[tid + off];
        __syncthreads();
    }
    if (tid == 0 && out_size >= NQ + 3) {
        float mse = (float)(sd[0] / (double)NQ);
        out[NQ + 0] = mse + 0.25f * mse;
        out[NQ + 1] = mse;
        out[NQ + 2] = mse;
    }
}

__global__ void k_indices(float* __restrict__ out, int out_size) {
    int i = blockIdx.x * blockDim.x + threadIdx.x;
    if (i < NPTS && out_size >= NQ + 3 + NPTS)
        out[NQ + 3 + i] = (float)g_enc[i];
}

extern "C" void kernel_launch(void* const* d_in, const int* in_sizes, int n_in,
                              void* d_out, int out_size) {
    const float* x   = (const float*)d_in[0];
    const float* emb = (const float*)d_in[1];
    if (n_in >= 2 && in_sizes[0] == KK * DDIM && in_sizes[1] == NQ) {
        const float* tmp = x; x = emb; emb = tmp;
    }
    float* out = (float*)d_out;
    int do_store = (out_size >= NQ) ? 1 : 0;

    static int attr_set = 0;
    if (!attr_set) {
        cudaFuncSetAttribute(k_gemm, cudaFuncAttributeMaxDynamicSharedMemorySize, GEMM_DSMEM);
        attr_set = 1;
    }

    k_init<<<1, 1>>>();
    k_prep_e<<<KK, 256>>>(emb);
    k_prep_x<<<dim3(TT / 32, DDIM / 32, BN), dim3(32, 8)>>>(x);
    k_gemm<<<NPTS / 128, 256, GEMM_DSMEM>>>();
    k_passB<<<256, 128>>>(x, emb);
    k_quant<<<NQ / (256 * 4), 256>>>(x, emb, out, do_store);
    k_scalars<<<1, 256>>>(out, out_size);
    k_indices<<<NPTS / 256, 256>>>(out, out_size);
}

// round 5
// speedup vs baseline: 5.4407x; 1.0175x over previous
#include <cuda_runtime.h>
#include <cuda_bf16.h>
#include <math.h>
#include <stdint.h>

// Problem constants
#define BN 16
#define DDIM 256
#define TT 2048
#define KK 1024
#define NPTS (BN*TT)        // 32768 points
#define NQ (BN*DDIM*TT)     // 8388608 elements
#define DELTA_TC 1e-5f      // bf16 3-term split score error ~1e-7; 100x margin

// ---------------- Device scratch ----------------
__device__ __nv_bfloat16 g_xhi[(size_t)NPTS * DDIM];
__device__ __nv_bfloat16 g_xlo[(size_t)NPTS * DDIM];
__device__ __nv_bfloat16 g_ehi[KK * DDIM];
__device__ __nv_bfloat16 g_elo[KK * DDIM];
__device__ float  g_c2[KK];
__device__ float  g_best[NPTS];
__device__ int    g_enc[NPTS];
__device__ int    g_nflag;
__device__ int    g_flags[NPTS];
__device__ double g_bsum[8192];

// ---------------- baseline-PTX helpers ----------------
__device__ __forceinline__ uint32_t smem_u32(const void* p) {
    uint32_t a;
    asm("{ .reg .u64 t; cvta.to.shared.u64 t, %1; cvt.u32.u64 %0, t; }" : "=r"(a) : "l"(p));
    return a;
}
__device__ __forceinline__ void cpasync16(uint32_t dst, const void* src) {
    asm volatile("cp.async.cg.shared.global [%0], [%1], 16;"
                 :: "r"(dst), "l"(__cvta_generic_to_global(src)) : "memory");
}
#define CP_COMMIT() asm volatile("cp.async.commit_group;" ::: "memory")
#define CP_WAIT0()  asm volatile("cp.async.wait_group 0;" ::: "memory")

__device__ __forceinline__ void ldm_x4(uint32_t a, uint32_t& r0, uint32_t& r1,
                                       uint32_t& r2, uint32_t& r3) {
    asm volatile("ldmatrix.sync.aligned.m8n8.x4.shared.b16 {%0,%1,%2,%3}, [%4];"
                 : "=r"(r0), "=r"(r1), "=r"(r2), "=r"(r3) : "r"(a));
}
__device__ __forceinline__ void ldm_x2(uint32_t a, uint32_t& r0, uint32_t& r1) {
    asm volatile("ldmatrix.sync.aligned.m8n8.x2.shared.b16 {%0,%1}, [%2];"
                 : "=r"(r0), "=r"(r1) : "r"(a));
}
__device__ __forceinline__ void mma_bf16(float* d, const uint32_t* a,
                                         uint32_t b0, uint32_t b1) {
    asm volatile("mma.sync.aligned.m16n8k16.row.col.f32.bf16.bf16.f32 "
                 "{%0,%1,%2,%3}, {%4,%5,%6,%7}, {%8,%9}, {%0,%1,%2,%3};"
                 : "+f"(d[0]), "+f"(d[1]), "+f"(d[2]), "+f"(d[3])
                 : "r"(a[0]), "r"(a[1]), "r"(a[2]), "r"(a[3]), "r"(b0), "r"(b1));
}

// ---------------- prep: bf16 hi/lo splits + ||e||^2 (+ flag init) ----------------
__global__ __launch_bounds__(256) void k_prep_e(const float* __restrict__ emb) {
    __shared__ float red[256];
    int k = blockIdx.x, d = threadIdx.x;
    if (k == 0 && d == 0) g_nflag = 0;
    float v = emb[k * DDIM + d];
    __nv_bfloat16 hi = __float2bfloat16(v);
    float hf = __bfloat162float(hi);
    __nv_bfloat16 lo = __float2bfloat16(v - hf);
    g_ehi[k * DDIM + d] = hi;
    g_elo[k * DDIM + d] = lo;
    red[d] = v * v;
    __syncthreads();
    for (int off = 128; off > 0; off >>= 1) {
        if (d < off) red[d] += red[d + off];
        __syncthreads();
    }
    if (d == 0) g_c2[k] = red[0];
}

__global__ __launch_bounds__(256) void k_prep_x(const float* __restrict__ x) {
    __shared__ float tile[32][33];
    int t0 = blockIdx.x * 32, d0 = blockIdx.y * 32, b = blockIdx.z;
    int tx = threadIdx.x, ty = threadIdx.y;
    #pragma unroll
    for (int j = 0; j < 4; j++) {
        int r = ty + j * 8;
        tile[r][tx] = x[((size_t)(b * DDIM + d0 + r)) * TT + t0 + tx];
    }
    __syncthreads();
    #pragma unroll
    for (int j = 0; j < 4; j++) {
        int r = ty + j * 8;
        size_t n = (size_t)b * TT + t0 + r;
        float v = tile[tx][r];
        __nv_bfloat16 hi = __float2bfloat16(v);
        float hf = __bfloat162float(hi);
        __nv_bfloat16 lo = __float2bfloat16(v - hf);
        g_xhi[n * DDIM + d0 + tx] = hi;
        g_xlo[n * DDIM + d0 + tx] = lo;
    }
}

// ---------------- Pass A: mma.sync bf16 3-term GEMM + fused argmin ----------------
#define ROWB 80                  // bytes per smem row (32 b16 + 8 pad)
#define MATB (128 * ROWB)        // 10240 B per matrix chunk
#define BUFB (4 * MATB)          // Ahi,Alo,Bhi,Blo
#define C2OFF (2 * BUFB)         // 81920
#define GEMM_DSMEM (C2OFF + KK * 4)

__device__ __forceinline__ void issue_chunk(int q, uint32_t base, int tid, int m0) {
    int ph = q >> 3, kc = q & 7;
    const __nv_bfloat16* xh = g_xhi + (size_t)m0 * DDIM;
    const __nv_bfloat16* xl = g_xlo + (size_t)m0 * DDIM;
    const __nv_bfloat16* eh = g_ehi + (size_t)(ph * 128) * DDIM;
    const __nv_bfloat16* el = g_elo + (size_t)(ph * 128) * DDIM;
    #pragma unroll
    for (int it = 0; it < 2; it++) {
        int idx = tid + it * 256;          // 0..511
        int row = idx >> 2, c16 = idx & 3;
        int gof = row * DDIM + kc * 32 + c16 * 8;
        uint32_t so = (uint32_t)(row * ROWB + c16 * 16);
        cpasync16(base + 0 * MATB + so, xh + gof);
        cpasync16(base + 1 * MATB + so, xl + gof);
        cpasync16(base + 2 * MATB + so, eh + gof);
        cpasync16(base + 3 * MATB + so, el + gof);
    }
}

__global__ void __launch_bounds__(256, 2) k_gemm() {
    extern __shared__ char dsm[];
    __shared__ float s_mb[2][128];
    __shared__ float s_ms[2][128];
    __shared__ int   s_mi[2][128];

    const uint32_t smb = smem_u32(dsm);
    float* c2s = (float*)(dsm + C2OFF);

    const int tid = threadIdx.x;
    const int wid = tid >> 5;
    const int lane = tid & 31;
    const int wm = wid >> 1;       // 0..3 (M)
    const int wn = wid & 1;        // 0..1 (N)
    const int m0 = blockIdx.x * 128;

    for (int i = tid; i < KK; i += 256) c2s[i] = g_c2[i];

    const int a_row = lane & 15;
    const int a_c8  = (lane >> 4) * 8;
    const int b_row = lane & 7;
    const int b_c8  = ((lane >> 3) & 1) * 8;

    float best[4] = {1e30f, 1e30f, 1e30f, 1e30f};
    float sec[4]  = {1e30f, 1e30f, 1e30f, 1e30f};
    int   bidx[4] = {0, 0, 0, 0};

    issue_chunk(0, smb, tid, m0);
    CP_COMMIT();
    int buf = 0;

    for (int ph = 0; ph < 8; ph++) {
        float acc[2][8][4];
        #pragma unroll
        for (int mt = 0; mt < 2; mt++)
            #pragma unroll
            for (int nt = 0; nt < 8; nt++)
                #pragma unroll
                for (int r = 0; r < 4; r++) acc[mt][nt][r] = 0.f;

        for (int kc = 0; kc < 8; kc++) {
            CP_WAIT0();
            __syncthreads();
            int q = ph * 8 + kc;
            if (q < 63) {
                issue_chunk(q + 1, smb + (uint32_t)((buf ^ 1) * BUFB), tid, m0);
                CP_COMMIT();
            }

            const uint32_t ab  = smb + (uint32_t)(buf * BUFB);
            const uint32_t alb = ab + MATB;
            const uint32_t bb  = ab + 2 * MATB;
            const uint32_t blb = ab + 3 * MATB;

            #pragma unroll
            for (int ks = 0; ks < 2; ks++) {
                const int kb = ks * 16;
                uint32_t ao0 = (uint32_t)((wm * 32 + a_row) * ROWB + (kb + a_c8) * 2);
                uint32_t ao1 = (uint32_t)((wm * 32 + 16 + a_row) * ROWB + (kb + a_c8) * 2);
                uint32_t ah0[4], ah1[4], al0[4], al1[4];
                ldm_x4(ab + ao0,  ah0[0], ah0[1], ah0[2], ah0[3]);
                ldm_x4(ab + ao1,  ah1[0], ah1[1], ah1[2], ah1[3]);
                ldm_x4(alb + ao0, al0[0], al0[1], al0[2], al0[3]);
                ldm_x4(alb + ao1, al1[0], al1[1], al1[2], al1[3]);

                #pragma unroll
                for (int half = 0; half < 2; half++) {
                    // batch-load B fragments for 4 nt (hi + lo), THEN run
                    // 24 MMAs ordered term-major so same-acc chains are 8 apart.
                    uint32_t bh[4][2], bl[4][2];
                    #pragma unroll
                    for (int j = 0; j < 4; j++) {
                        int nt = half * 4 + j;
                        uint32_t bo = (uint32_t)((wn * 64 + nt * 8 + b_row) * ROWB + (kb + b_c8) * 2);
                        ldm_x2(bb + bo,  bh[j][0], bh[j][1]);
                        ldm_x2(blb + bo, bl[j][0], bl[j][1]);
                    }
                    #pragma unroll
                    for (int j = 0; j < 4; j++) {
                        int nt = half * 4 + j;
                        mma_bf16(acc[0][nt], ah0, bh[j][0], bh[j][1]);
                        mma_bf16(acc[1][nt], ah1, bh[j][0], bh[j][1]);
                    }
                    #pragma unroll
                    for (int j = 0; j < 4; j++) {
                        int nt = half * 4 + j;
                        mma_bf16(acc[0][nt], al0, bh[j][0], bh[j][1]);
                        mma_bf16(acc[1][nt], al1, bh[j][0], bh[j][1]);
                    }
                    #pragma unroll
                    for (int j = 0; j < 4; j++) {
                        int nt = half * 4 + j;
                        mma_bf16(acc[0][nt], ah0, bl[j][0], bl[j][1]);
                        mma_bf16(acc[1][nt], ah1, bl[j][0], bl[j][1]);
                    }
                }
            }
            __syncthreads();
            buf ^= 1;
        }

        // epilogue: scores + argmin update (rows: wm*32 + mt*16 + h*8 + lane/4)
        #pragma unroll
        for (int mt = 0; mt < 2; mt++) {
            #pragma unroll
            for (int h = 0; h < 2; h++) {
                const int slot = mt * 2 + h;
                #pragma unroll
                for (int nt = 0; nt < 8; nt++) {
                    int k0 = ph * 128 + wn * 64 + nt * 8 + (lane & 3) * 2;
                    float s0 = fmaf(-2.f, acc[mt][nt][2 * h + 0], c2s[k0]);
                    float s1 = fmaf(-2.f, acc[mt][nt][2 * h + 1], c2s[k0 + 1]);
                    if (s0 < best[slot]) { sec[slot] = best[slot]; best[slot] = s0; bidx[slot] = k0; }
                    else if (s0 < sec[slot]) sec[slot] = s0;
                    if (s1 < best[slot]) { sec[slot] = best[slot]; best[slot] = s1; bidx[slot] = k0 + 1; }
                    else if (s1 < sec[slot]) sec[slot] = s1;
                }
            }
        }
    }

    // merge: quad shfl (4 lanes share a row), then the 2 N-warps via smem
    #pragma unroll
    for (int slot = 0; slot < 4; slot++) {
        float b = best[slot], s = sec[slot];
        int i = bidx[slot];
        #pragma unroll
        for (int off = 1; off <= 2; off <<= 1) {
            float ob = __shfl_xor_sync(0xffffffffu, b, off);
            float os = __shfl_xor_sync(0xffffffffu, s, off);
            int   oi = __shfl_xor_sync(0xffffffffu, i, off);
            if (ob < b) { s = fminf(os, b); b = ob; i = oi; }
            else { s = fminf(s, ob); if (ob == b && oi < i) i = oi; }
        }
        if ((lane & 3) == 0) {
            int mt = slot >> 1, h = slot & 1;
            int row = wm * 32 + mt * 16 + h * 8 + (lane >> 2);
            s_mb[wn][row] = b; s_ms[wn][row] = s; s_mi[wn][row] = i;
        }
    }
    __syncthreads();
    if (tid < 128) {
        float b0 = s_mb[0][tid], s0 = s_ms[0][tid];
        int i0 = s_mi[0][tid];
        float b1 = s_mb[1][tid], s1 = s_ms[1][tid];
        int i1 = s_mi[1][tid];
        float b, s; int i;
        if (b1 < b0) { b = b1; i = i1; s = fminf(s1, b0); }
        else { b = b0; i = (b1 == b0 && i1 < i0) ? i1 : i0; s = fminf(s0, b1); }
        int n = m0 + tid;
        g_enc[n] = i;
        g_best[n] = b;
        if (s - b < DELTA_TC) {
            int pos = atomicAdd(&g_nflag, 1);
            g_flags[pos] = n;
        }
    }
}

// ---------------- Pass B: exact fp64 re-resolution for near-ties ----------------
__global__ __launch_bounds__(128) void k_passB(const float* __restrict__ x,
                                               const float* __restrict__ emb) {
    __shared__ float  xs[DDIM];
    __shared__ double rdv[128];
    __shared__ int    rk[128];
    const int tid = threadIdx.x;
    const int nf = g_nflag;

    for (int fi = blockIdx.x; fi < nf; fi += gridDim.x) {
        int n = g_flags[fi];
        int b = n / TT, t = n % TT;
        __syncthreads();
        for (int d = tid; d < DDIM; d += 128)
            xs[d] = x[(size_t)b * DDIM * TT + (size_t)d * TT + t];
        __syncthreads();

        float thresh = g_best[n] + 2e-4f;
        double bd = 1e300;
        int    bk = KK;
        for (int k = tid; k < KK; k += 128) {
            const float4* er = (const float4*)&emb[k * DDIM];
            float dot = 0.f;
            #pragma unroll 4
            for (int d4 = 0; d4 < 64; d4++) {
                float4 e4 = er[d4];
                dot = fmaf(xs[d4 * 4 + 0], e4.x, dot);
                dot = fmaf(xs[d4 * 4 + 1], e4.y, dot);
                dot = fmaf(xs[d4 * 4 + 2], e4.z, dot);
                dot = fmaf(xs[d4 * 4 + 3], e4.w, dot);
            }
            float s = fmaf(-2.f, dot, g_c2[k]);
            if (s <= thresh) {
                double d2 = 0.0;
                for (int d = 0; d < DDIM; d++) {
                    double diff = (double)xs[d] - (double)emb[k * DDIM + d];
                    d2 = fma(diff, diff, d2);
                }
                if (d2 < bd || (d2 == bd && k < bk)) { bd = d2; bk = k; }
            }
        }
        rdv[tid] = bd; rk[tid] = bk;
        __syncthreads();
        for (int off = 64; off > 0; off >>= 1) {
            if (tid < off) {
                double od = rdv[tid + off];
                int    ok = rk[tid + off];
                if (od < rdv[tid] || (od == rdv[tid] && ok < rk[tid])) {
                    rdv[tid] = od; rk[tid] = ok;
                }
            }
            __syncthreads();
        }
        if (tid == 0) g_enc[n] = rk[0];
    }
}

// ---------------- quantized_st + MSE partials ----------------
__global__ __launch_bounds__(256) void k_quant(const float* __restrict__ x,
                                               const float* __restrict__ emb,
                                               float* __restrict__ out,
                                               int do_store) {
    __shared__ float sf[256];
    const int tid = threadIdx.x;
    const int gi = blockIdx.x * 256 + tid;
    const size_t base = (size_t)gi * 4;

    int t = (int)(base % TT);
    size_t tmp = base / TT;
    int d = (int)(tmp % DDIM);
    int b = (int)(tmp / DDIM);

    float4 xv = *(const float4*)&x[base];
    int nb = b * TT + t;
    int i0 = g_enc[nb + 0];
    int i1 = g_enc[nb + 1];
    int i2 = g_enc[nb + 2];
    int i3 = g_enc[nb + 3];
    float q0 = __ldg(&emb[i0 * DDIM + d]);
    float q1 = __ldg(&emb[i1 * DDIM + d]);
    float q2 = __ldg(&emb[i2 * DDIM + d]);
    float q3 = __ldg(&emb[i3 * DDIM + d]);
    float d0 = q0 - xv.x;
    float d1 = q1 - xv.y;
    float d2 = q2 - xv.z;
    float d3 = q3 - xv.w;
    if (do_store) {
        float4 ov = make_float4(xv.x + d0, xv.y + d1, xv.z + d2, xv.w + d3);
        *(float4*)&out[base] = ov;
    }
    float loc = d0 * d0;
    loc = fmaf(d1, d1, loc);
    loc = fmaf(d2, d2, loc);
    loc = fmaf(d3, d3, loc);

    sf[tid] = loc;
    __syncthreads();
    for (int off = 128; off > 0; off >>= 1) {
        if (tid < off) sf[tid] += sf[tid + off];
        __syncthreads();
    }
    if (tid == 0) g_bsum[blockIdx.x] = (double)sf[0];
}

// Block 0: deterministic final MSE reduce + scalars. Blocks 1..128: indices.
__global__ void k_finish(float* __restrict__ out, int out_size) {
    if (blockIdx.x == 0) {
        __shared__ double sd[256];
        const int tid = threadIdx.x;
        double loc = 0.0;
        for (int i = tid; i < 8192; i += 256) loc += g_bsum[i];
        sd[tid] = loc;
        __syncthreads();
        for (int off = 128; off > 0; off >>= 1) {
            if (tid < off) sd[tid] += sd[tid + off];
            __syncthreads();
        }
        if (tid == 0 && out_size >= NQ + 3) {
            float mse = (float)(sd[0] / (double)NQ);
            out[NQ + 0] = mse + 0.25f * mse;
            out[NQ + 1] = mse;
            out[NQ + 2] = mse;
        }
    } else {
        int i = (blockIdx.x - 1) * 256 + threadIdx.x;
        if (i < NPTS && out_size >= NQ + 3 + NPTS)
            out[NQ + 3 + i] = (float)g_enc[i];
    }
}

extern "C" void kernel_launch(void* const* d_in, const int* in_sizes, int n_in,
                              void* d_out, int out_size) {
    const float* x   = (const float*)d_in[0];
    const float* emb = (const float*)d_in[1];
    if (n_in >= 2 && in_sizes[0] == KK * DDIM && in_sizes[1] == NQ) {
        const float* tmp = x; x = emb; emb = tmp;
    }
    float* out = (float*)d_out;
    int do_store = (out_size >= NQ) ? 1 : 0;

    static int attr_set = 0;
    if (!attr_set) {
        cudaFuncSetAttribute(k_gemm, cudaFuncAttributeMaxDynamicSharedMemorySize, GEMM_DSMEM);
        attr_set = 1;
    }

    k_prep_e<<<KK, 256>>>(emb);
    k_prep_x<<<dim3(TT / 32, DDIM / 32, BN), dim3(32, 8)>>>(x);
    k_gemm<<<NPTS / 128, 256, GEMM_DSMEM>>>();
    k_passB<<<256, 128>>>(x, emb);
    k_quant<<<NQ / (256 * 4), 256>>>(x, emb, out, do_store);
    k_finish<<<1 + NPTS / 256, 256>>>(out, out_size);
}

// round 6
// speedup vs baseline: 7.6093x; 1.3986x over previous
#include <cuda_runtime.h>
#include <cuda_bf16.h>
#include <math.h>
#include <stdint.h>

// Problem constants
#define BN 16
#define DDIM 256
#define TT 2048
#define KK 1024
#define NPTS (BN*TT)        // 32768 points
#define NQ (BN*DDIM*TT)     // 8388608 elements
#define DELTA_TC 1e-5f      // bf16 3-term split score error ~1e-7; 100x margin

// ---------------- Device scratch ----------------
__device__ __nv_bfloat16 g_xhi[(size_t)NPTS * DDIM];
__device__ __nv_bfloat16 g_xlo[(size_t)NPTS * DDIM];
__device__ __nv_bfloat16 g_ehi[KK * DDIM];
__device__ __nv_bfloat16 g_elo[KK * DDIM];
__device__ float  g_c2[KK];
__device__ int    g_enc[NPTS];
__device__ int    g_sidx[NPTS];      // second-best index (for flagged points)
__device__ int    g_nflag;
__device__ int    g_flags[NPTS];
__device__ double g_bsum[8192];

// ---------------- baseline-PTX helpers ----------------
__device__ __forceinline__ uint32_t smem_u32(const void* p) {
    uint32_t a;
    asm("{ .reg .u64 t; cvta.to.shared.u64 t, %1; cvt.u32.u64 %0, t; }" : "=r"(a) : "l"(p));
    return a;
}
__device__ __forceinline__ void cpasync16(uint32_t dst, const void* src) {
    asm volatile("cp.async.cg.shared.global [%0], [%1], 16;"
                 :: "r"(dst), "l"(__cvta_generic_to_global(src)) : "memory");
}
#define CP_COMMIT() asm volatile("cp.async.commit_group;" ::: "memory")
#define CP_WAIT0()  asm volatile("cp.async.wait_group 0;" ::: "memory")

__device__ __forceinline__ void ldm_x4(uint32_t a, uint32_t& r0, uint32_t& r1,
                                       uint32_t& r2, uint32_t& r3) {
    asm volatile("ldmatrix.sync.aligned.m8n8.x4.shared.b16 {%0,%1,%2,%3}, [%4];"
                 : "=r"(r0), "=r"(r1), "=r"(r2), "=r"(r3) : "r"(a));
}
__device__ __forceinline__ void ldm_x2(uint32_t a, uint32_t& r0, uint32_t& r1) {
    asm volatile("ldmatrix.sync.aligned.m8n8.x2.shared.b16 {%0,%1}, [%2];"
                 : "=r"(r0), "=r"(r1) : "r"(a));
}
__device__ __forceinline__ void mma_bf16(float* d, const uint32_t* a,
                                         uint32_t b0, uint32_t b1) {
    asm volatile("mma.sync.aligned.m16n8k16.row.col.f32.bf16.bf16.f32 "
                 "{%0,%1,%2,%3}, {%4,%5,%6,%7}, {%8,%9}, {%0,%1,%2,%3};"
                 : "+f"(d[0]), "+f"(d[1]), "+f"(d[2]), "+f"(d[3])
                 : "r"(a[0]), "r"(a[1]), "r"(a[2]), "r"(a[3]), "r"(b0), "r"(b1));
}

// top-2 merge: (b1,i1,s1,si1) (self, modified) with (b2,i2,s2,si2)
__device__ __forceinline__ void merge_top2(float& b1, int& i1, float& s1, int& si1,
                                           float b2, int i2, float s2, int si2) {
    // order pairs (value, idx) lexicographically
    if (b2 < b1 || (b2 == b1 && i2 < i1)) {
        // b2 is new best; sec = min of (b1,i1) and (s2,si2)
        float ob = b1; int oi = i1;
        b1 = b2; i1 = i2;
        if (ob < s2 || (ob == s2 && oi < si2)) { s1 = ob; si1 = oi; }
        else { s1 = s2; si1 = si2; }
    } else {
        // b1 stays best; sec = min of (s1,si1) and (b2,i2)
        if (b2 < s1 || (b2 == s1 && i2 < si1)) { s1 = b2; si1 = i2; }
    }
}

// ---------------- prep: bf16 hi/lo splits + ||e||^2 (+ flag init) ----------------
__global__ __launch_bounds__(256) void k_prep_e(const float* __restrict__ emb) {
    __shared__ float red[256];
    int k = blockIdx.x, d = threadIdx.x;
    if (k == 0 && d == 0) g_nflag = 0;
    float v = emb[k * DDIM + d];
    __nv_bfloat16 hi = __float2bfloat16(v);
    float hf = __bfloat162float(hi);
    __nv_bfloat16 lo = __float2bfloat16(v - hf);
    g_ehi[k * DDIM + d] = hi;
    g_elo[k * DDIM + d] = lo;
    red[d] = v * v;
    __syncthreads();
    for (int off = 128; off > 0; off >>= 1) {
        if (d < off) red[d] += red[d + off];
        __syncthreads();
    }
    if (d == 0) g_c2[k] = red[0];
}

__global__ __launch_bounds__(256) void k_prep_x(const float* __restrict__ x) {
    __shared__ float tile[32][33];
    int t0 = blockIdx.x * 32, d0 = blockIdx.y * 32, b = blockIdx.z;
    int tx = threadIdx.x, ty = threadIdx.y;
    #pragma unroll
    for (int j = 0; j < 4; j++) {
        int r = ty + j * 8;
        tile[r][tx] = x[((size_t)(b * DDIM + d0 + r)) * TT + t0 + tx];
    }
    __syncthreads();
    #pragma unroll
    for (int j = 0; j < 4; j++) {
        int r = ty + j * 8;
        size_t n = (size_t)b * TT + t0 + r;
        float v = tile[tx][r];
        __nv_bfloat16 hi = __float2bfloat16(v);
        float hf = __bfloat162float(hi);
        __nv_bfloat16 lo = __float2bfloat16(v - hf);
        g_xhi[n * DDIM + d0 + tx] = hi;
        g_xlo[n * DDIM + d0 + tx] = lo;
    }
}

// ---------------- Pass A: mma.sync bf16 3-term GEMM + fused argmin ----------------
#define ROWB 80                  // bytes per smem row (32 b16 + 8 pad)
#define MATB (128 * ROWB)        // 10240 B per matrix chunk
#define BUFB (4 * MATB)          // Ahi,Alo,Bhi,Blo
#define C2OFF (2 * BUFB)         // 81920
#define GEMM_DSMEM (C2OFF + KK * 4)

__device__ __forceinline__ void issue_chunk(int q, uint32_t base, int tid, int m0) {
    int ph = q >> 3, kc = q & 7;
    const __nv_bfloat16* xh = g_xhi + (size_t)m0 * DDIM;
    const __nv_bfloat16* xl = g_xlo + (size_t)m0 * DDIM;
    const __nv_bfloat16* eh = g_ehi + (size_t)(ph * 128) * DDIM;
    const __nv_bfloat16* el = g_elo + (size_t)(ph * 128) * DDIM;
    #pragma unroll
    for (int it = 0; it < 2; it++) {
        int idx = tid + it * 256;          // 0..511
        int row = idx >> 2, c16 = idx & 3;
        int gof = row * DDIM + kc * 32 + c16 * 8;
        uint32_t so = (uint32_t)(row * ROWB + c16 * 16);
        cpasync16(base + 0 * MATB + so, xh + gof);
        cpasync16(base + 1 * MATB + so, xl + gof);
        cpasync16(base + 2 * MATB + so, eh + gof);
        cpasync16(base + 3 * MATB + so, el + gof);
    }
}

__global__ void __launch_bounds__(256, 2) k_gemm() {
    extern __shared__ char dsm[];
    __shared__ float s_mb[2][128];
    __shared__ float s_ms[2][128];
    __shared__ int   s_mi[2][128];
    __shared__ int   s_msi[2][128];

    const uint32_t smb = smem_u32(dsm);
    float* c2s = (float*)(dsm + C2OFF);

    const int tid = threadIdx.x;
    const int wid = tid >> 5;
    const int lane = tid & 31;
    const int wm = wid >> 1;       // 0..3 (M)
    const int wn = wid & 1;        // 0..1 (N)
    const int m0 = blockIdx.x * 128;

    for (int i = tid; i < KK; i += 256) c2s[i] = g_c2[i];

    const int a_row = lane & 15;
    const int a_c8  = (lane >> 4) * 8;
    const int b_row = lane & 7;
    const int b_c8  = ((lane >> 3) & 1) * 8;

    float best[4] = {1e30f, 1e30f, 1e30f, 1e30f};
    float sec[4]  = {1e30f, 1e30f, 1e30f, 1e30f};
    int   bidx[4] = {0, 0, 0, 0};
    int   sidx[4] = {0, 0, 0, 0};

    issue_chunk(0, smb, tid, m0);
    CP_COMMIT();
    int buf = 0;

    for (int ph = 0; ph < 8; ph++) {
        float acc[2][8][4];
        #pragma unroll
        for (int mt = 0; mt < 2; mt++)
            #pragma unroll
            for (int nt = 0; nt < 8; nt++)
                #pragma unroll
                for (int r = 0; r < 4; r++) acc[mt][nt][r] = 0.f;

        for (int kc = 0; kc < 8; kc++) {
            CP_WAIT0();
            __syncthreads();
            int q = ph * 8 + kc;
            if (q < 63) {
                issue_chunk(q + 1, smb + (uint32_t)((buf ^ 1) * BUFB), tid, m0);
                CP_COMMIT();
            }

            const uint32_t ab  = smb + (uint32_t)(buf * BUFB);
            const uint32_t alb = ab + MATB;
            const uint32_t bb  = ab + 2 * MATB;
            const uint32_t blb = ab + 3 * MATB;

            #pragma unroll
            for (int ks = 0; ks < 2; ks++) {
                const int kb = ks * 16;
                uint32_t ao0 = (uint32_t)((wm * 32 + a_row) * ROWB + (kb + a_c8) * 2);
                uint32_t ao1 = (uint32_t)((wm * 32 + 16 + a_row) * ROWB + (kb + a_c8) * 2);
                uint32_t ah0[4], ah1[4], al0[4], al1[4];
                ldm_x4(ab + ao0,  ah0[0], ah0[1], ah0[2], ah0[3]);
                ldm_x4(ab + ao1,  ah1[0], ah1[1], ah1[2], ah1[3]);
                ldm_x4(alb + ao0, al0[0], al0[1], al0[2], al0[3]);
                ldm_x4(alb + ao1, al1[0], al1[1], al1[2], al1[3]);

                #pragma unroll
                for (int half = 0; half < 2; half++) {
                    uint32_t bh[4][2], bl[4][2];
                    #pragma unroll
                    for (int j = 0; j < 4; j++) {
                        int nt = half * 4 + j;
                        uint32_t bo = (uint32_t)((wn * 64 + nt * 8 + b_row) * ROWB + (kb + b_c8) * 2);
                        ldm_x2(bb + bo,  bh[j][0], bh[j][1]);
                        ldm_x2(blb + bo, bl[j][0], bl[j][1]);
                    }
                    #pragma unroll
                    for (int j = 0; j < 4; j++) {
                        int nt = half * 4 + j;
                        mma_bf16(acc[0][nt], ah0, bh[j][0], bh[j][1]);
                        mma_bf16(acc[1][nt], ah1, bh[j][0], bh[j][1]);
                    }
                    #pragma unroll
                    for (int j = 0; j < 4; j++) {
                        int nt = half * 4 + j;
                        mma_bf16(acc[0][nt], al0, bh[j][0], bh[j][1]);
                        mma_bf16(acc[1][nt], al1, bh[j][0], bh[j][1]);
                    }
                    #pragma unroll
                    for (int j = 0; j < 4; j++) {
                        int nt = half * 4 + j;
                        mma_bf16(acc[0][nt], ah0, bl[j][0], bl[j][1]);
                        mma_bf16(acc[1][nt], ah1, bl[j][0], bl[j][1]);
                    }
                }
            }
            __syncthreads();
            buf ^= 1;
        }

        // epilogue: scores + top-2 update (rows: wm*32 + mt*16 + h*8 + lane/4)
        #pragma unroll
        for (int mt = 0; mt < 2; mt++) {
            #pragma unroll
            for (int h = 0; h < 2; h++) {
                const int slot = mt * 2 + h;
                #pragma unroll
                for (int nt = 0; nt < 8; nt++) {
                    int k0 = ph * 128 + wn * 64 + nt * 8 + (lane & 3) * 2;
                    float s0 = fmaf(-2.f, acc[mt][nt][2 * h + 0], c2s[k0]);
                    float s1 = fmaf(-2.f, acc[mt][nt][2 * h + 1], c2s[k0 + 1]);
                    if (s0 < best[slot]) {
                        sec[slot] = best[slot]; sidx[slot] = bidx[slot];
                        best[slot] = s0; bidx[slot] = k0;
                    } else if (s0 < sec[slot]) { sec[slot] = s0; sidx[slot] = k0; }
                    if (s1 < best[slot]) {
                        sec[slot] = best[slot]; sidx[slot] = bidx[slot];
                        best[slot] = s1; bidx[slot] = k0 + 1;
                    } else if (s1 < sec[slot]) { sec[slot] = s1; sidx[slot] = k0 + 1; }
                }
            }
        }
    }

    // merge: quad shfl (4 lanes share a row), then the 2 N-warps via smem
    #pragma unroll
    for (int slot = 0; slot < 4; slot++) {
        float b = best[slot], s = sec[slot];
        int i = bidx[slot], si = sidx[slot];
        #pragma unroll
        for (int off = 1; off <= 2; off <<= 1) {
            float ob  = __shfl_xor_sync(0xffffffffu, b, off);
            float os  = __shfl_xor_sync(0xffffffffu, s, off);
            int   oi  = __shfl_xor_sync(0xffffffffu, i, off);
            int   osi = __shfl_xor_sync(0xffffffffu, si, off);
            merge_top2(b, i, s, si, ob, oi, os, osi);
        }
        if ((lane & 3) == 0) {
            int mt = slot >> 1, h = slot & 1;
            int row = wm * 32 + mt * 16 + h * 8 + (lane >> 2);
            s_mb[wn][row] = b; s_ms[wn][row] = s;
            s_mi[wn][row] = i; s_msi[wn][row] = si;
        }
    }
    __syncthreads();
    if (tid < 128) {
        float b = s_mb[0][tid], s = s_ms[0][tid];
        int i = s_mi[0][tid], si = s_msi[0][tid];
        merge_top2(b, i, s, si, s_mb[1][tid], s_mi[1][tid], s_ms[1][tid], s_msi[1][tid]);
        int n = m0 + tid;
        g_enc[n] = i;
        if (s - b < DELTA_TC) {
            g_sidx[n] = si;
            int pos = atomicAdd(&g_nflag, 1);
            g_flags[pos] = n;
        }
    }
}

// ---------------- Pass B: exact fp64 top-2 compare, one warp per point ----------------
__global__ __launch_bounds__(256) void k_passB(const float* __restrict__ x,
                                               const float* __restrict__ emb) {
    const int nf = g_nflag;
    const int gw = (blockIdx.x * blockDim.x + threadIdx.x) >> 5;
    const int nw = (gridDim.x * blockDim.x) >> 5;
    const int lane = threadIdx.x & 31;

    for (int fi = gw; fi < nf; fi += nw) {
        int n = g_flags[fi];
        int i1 = g_enc[n], i2 = g_sidx[n];
        int b = n / TT, t = n % TT;
        const float* xb = x + (size_t)b * DDIM * TT + t;
        double a1 = 0.0, a2 = 0.0;
        #pragma unroll
        for (int j = 0; j < 8; j++) {
            int d = lane * 8 + j;
            double xv = (double)xb[(size_t)d * TT];
            double e1 = (double)emb[i1 * DDIM + d];
            double e2 = (double)emb[i2 * DDIM + d];
            double f1 = xv - e1, f2 = xv - e2;
            a1 = fma(f1, f1, a1);
            a2 = fma(f2, f2, a2);
        }
        #pragma unroll
        for (int off = 16; off > 0; off >>= 1) {
            a1 += __shfl_down_sync(0xffffffffu, a1, off);
            a2 += __shfl_down_sync(0xffffffffu, a2, off);
        }
        if (lane == 0) {
            if (a2 < a1 || (a2 == a1 && i2 < i1)) g_enc[n] = i2;
        }
    }
}

// ---------------- quantized_st + MSE partials ----------------
__global__ __launch_bounds__(256) void k_quant(const float* __restrict__ x,
                                               const float* __restrict__ emb,
                                               float* __restrict__ out,
                                               int do_store) {
    __shared__ float sf[256];
    const int tid = threadIdx.x;
    const int gi = blockIdx.x * 256 + tid;
    const size_t base = (size_t)gi * 4;

    int t = (int)(base % TT);
    size_t tmp = base / TT;
    int d = (int)(tmp % DDIM);
    int b = (int)(tmp / DDIM);

    float4 xv = *(const float4*)&x[base];
    int nb = b * TT + t;
    int i0 = g_enc[nb + 0];
    int i1 = g_enc[nb + 1];
    int i2 = g_enc[nb + 2];
    int i3 = g_enc[nb + 3];
    float q0 = __ldg(&emb[i0 * DDIM + d]);
    float q1 = __ldg(&emb[i1 * DDIM + d]);
    float q2 = __ldg(&emb[i2 * DDIM + d]);
    float q3 = __ldg(&emb[i3 * DDIM + d]);
    float d0 = q0 - xv.x;
    float d1 = q1 - xv.y;
    float d2 = q2 - xv.z;
    float d3 = q3 - xv.w;
    if (do_store) {
        float4 ov = make_float4(xv.x + d0, xv.y + d1, xv.z + d2, xv.w + d3);
        *(float4*)&out[base] = ov;
    }
    float loc = d0 * d0;
    loc = fmaf(d1, d1, loc);
    loc = fmaf(d2, d2, loc);
    loc = fmaf(d3, d3, loc);

    sf[tid] = loc;
    __syncthreads();
    for (int off = 128; off > 0; off >>= 1) {
        if (tid < off) sf[tid] += sf[tid + off];
        __syncthreads();
    }
    if (tid == 0) g_bsum[blockIdx.x] = (double)sf[0];
}

// Block 0: deterministic final MSE reduce + scalars. Blocks 1..128: indices.
__global__ void k_finish(float* __restrict__ out, int out_size) {
    if (blockIdx.x == 0) {
        __shared__ double sd[256];
        const int tid = threadIdx.x;
        double loc = 0.0;
        for (int i = tid; i < 8192; i += 256) loc += g_bsum[i];
        sd[tid] = loc;
        __syncthreads();
        for (int off = 128; off > 0; off >>= 1) {
            if (tid < off) sd[tid] += sd[tid + off];
            __syncthreads();
        }
        if (tid == 0 && out_size >= NQ + 3) {
            float mse = (float)(sd[0] / (double)NQ);
            out[NQ + 0] = mse + 0.25f * mse;
            out[NQ + 1] = mse;
            out[NQ + 2] = mse;
        }
    } else {
        int i = (blockIdx.x - 1) * 256 + threadIdx.x;
        if (i < NPTS && out_size >= NQ + 3 + NPTS)
            out[NQ + 3 + i] = (float)g_enc[i];
    }
}

extern "C" void kernel_launch(void* const* d_in, const int* in_sizes, int n_in,
                              void* d_out, int out_size) {
    const float* x   = (const float*)d_in[0];
    const float* emb = (const float*)d_in[1];
    if (n_in >= 2 && in_sizes[0] == KK * DDIM && in_sizes[1] == NQ) {
        const float* tmp = x; x = emb; emb = tmp;
    }
    float* out = (float*)d_out;
    int do_store = (out_size >= NQ) ? 1 : 0;

    static int attr_set = 0;
    if (!attr_set) {
        cudaFuncSetAttribute(k_gemm, cudaFuncAttributeMaxDynamicSharedMemorySize, GEMM_DSMEM);
        attr_set = 1;
    }

    k_prep_e<<<KK, 256>>>(emb);
    k_prep_x<<<dim3(TT / 32, DDIM / 32, BN), dim3(32, 8)>>>(x);
    k_gemm<<<NPTS / 128, 256, GEMM_DSMEM>>>();
    k_passB<<<128, 256>>>(x, emb);
    k_quant<<<NQ / (256 * 4), 256>>>(x, emb, out, do_store);
    k_finish<<<1 + NPTS / 256, 256>>>(out, out_size);
}

// round 7
// speedup vs baseline: 7.6702x; 1.0080x over previous
#include <cuda_runtime.h>
#include <cuda_bf16.h>
#include <math.h>
#include <stdint.h>

// Problem constants
#define BN 16
#define DDIM 256
#define TT 2048
#define KK 1024
#define NPTS (BN*TT)        // 32768 points
#define NQ (BN*DDIM*TT)     // 8388608 elements
#define DELTA_TC 1e-5f      // bf16 3-term split score error ~1e-7; 100x margin

// ---------------- Device scratch ----------------
__device__ __nv_bfloat16 g_xhi[(size_t)NPTS * DDIM];
__device__ __nv_bfloat16 g_xlo[(size_t)NPTS * DDIM];
__device__ __nv_bfloat16 g_ehi[KK * DDIM];
__device__ __nv_bfloat16 g_elo[KK * DDIM];
__device__ float  g_c2[KK];
__device__ int    g_enc[NPTS];
__device__ int    g_sidx[NPTS];      // second-best index (for flagged points)
__device__ int    g_nflag;
__device__ int    g_flags[NPTS];
__device__ double g_bsum[8192];

// ---------------- baseline-PTX helpers ----------------
__device__ __forceinline__ uint32_t smem_u32(const void* p) {
    uint32_t a;
    asm("{ .reg .u64 t; cvta.to.shared.u64 t, %1; cvt.u32.u64 %0, t; }" : "=r"(a) : "l"(p));
    return a;
}
__device__ __forceinline__ void cpasync16(uint32_t dst, const void* src) {
    asm volatile("cp.async.cg.shared.global [%0], [%1], 16;"
                 :: "r"(dst), "l"(__cvta_generic_to_global(src)) : "memory");
}
#define CP_COMMIT() asm volatile("cp.async.commit_group;" ::: "memory")
#define CP_WAIT0()  asm volatile("cp.async.wait_group 0;" ::: "memory")

__device__ __forceinline__ void ldm_x4(uint32_t a, uint32_t& r0, uint32_t& r1,
                                       uint32_t& r2, uint32_t& r3) {
    asm volatile("ldmatrix.sync.aligned.m8n8.x4.shared.b16 {%0,%1,%2,%3}, [%4];"
                 : "=r"(r0), "=r"(r1), "=r"(r2), "=r"(r3) : "r"(a));
}
__device__ __forceinline__ void mma_bf16(float* d, const uint32_t* a,
                                         uint32_t b0, uint32_t b1) {
    asm volatile("mma.sync.aligned.m16n8k16.row.col.f32.bf16.bf16.f32 "
                 "{%0,%1,%2,%3}, {%4,%5,%6,%7}, {%8,%9}, {%0,%1,%2,%3};"
                 : "+f"(d[0]), "+f"(d[1]), "+f"(d[2]), "+f"(d[3])
                 : "r"(a[0]), "r"(a[1]), "r"(a[2]), "r"(a[3]), "r"(b0), "r"(b1));
}

// top-2 merge: (b1,i1,s1,si1) (self, modified) with (b2,i2,s2,si2)
__device__ __forceinline__ void merge_top2(float& b1, int& i1, float& s1, int& si1,
                                           float b2, int i2, float s2, int si2) {
    if (b2 < b1 || (b2 == b1 && i2 < i1)) {
        float ob = b1; int oi = i1;
        b1 = b2; i1 = i2;
        if (ob < s2 || (ob == s2 && oi < si2)) { s1 = ob; si1 = oi; }
        else { s1 = s2; si1 = si2; }
    } else {
        if (b2 < s1 || (b2 == s1 && i2 < si1)) { s1 = b2; si1 = i2; }
    }
}

// ---------------- prep: bf16 hi/lo splits + ||e||^2 (+ flag init) ----------------
__global__ __launch_bounds__(256) void k_prep_e(const float* __restrict__ emb) {
    __shared__ float red[256];
    int k = blockIdx.x, d = threadIdx.x;
    if (k == 0 && d == 0) g_nflag = 0;
    float v = emb[k * DDIM + d];
    __nv_bfloat16 hi = __float2bfloat16(v);
    float hf = __bfloat162float(hi);
    __nv_bfloat16 lo = __float2bfloat16(v - hf);
    g_ehi[k * DDIM + d] = hi;
    g_elo[k * DDIM + d] = lo;
    red[d] = v * v;
    __syncthreads();
    for (int off = 128; off > 0; off >>= 1) {
        if (d < off) red[d] += red[d + off];
        __syncthreads();
    }
    if (d == 0) g_c2[k] = red[0];
}

__global__ __launch_bounds__(256) void k_prep_x(const float* __restrict__ x) {
    __shared__ float tile[32][33];
    int t0 = blockIdx.x * 32, d0 = blockIdx.y * 32, b = blockIdx.z;
    int tx = threadIdx.x, ty = threadIdx.y;
    #pragma unroll
    for (int j = 0; j < 4; j++) {
        int r = ty + j * 8;
        tile[r][tx] = x[((size_t)(b * DDIM + d0 + r)) * TT + t0 + tx];
    }
    __syncthreads();
    #pragma unroll
    for (int j = 0; j < 4; j++) {
        int r = ty + j * 8;
        size_t n = (size_t)b * TT + t0 + r;
        float v = tile[tx][r];
        __nv_bfloat16 hi = __float2bfloat16(v);
        float hf = __bfloat162float(hi);
        __nv_bfloat16 lo = __float2bfloat16(v - hf);
        g_xhi[n * DDIM + d0 + tx] = hi;
        g_xlo[n * DDIM + d0 + tx] = lo;
    }
}

// ---------------- Pass A: mma.sync bf16 3-term GEMM + fused argmin ----------------
#define ROWB 80                  // bytes per smem row (32 b16 + 8 pad)
#define MATB (128 * ROWB)        // 10240 B per matrix chunk
#define BUFB (4 * MATB)          // Ahi,Alo,Bhi,Blo
#define C2OFF (2 * BUFB)         // 81920
#define GEMM_DSMEM (C2OFF + KK * 4)

__device__ __forceinline__ void issue_chunk(int q, uint32_t base, int tid, int m0) {
    int ph = q >> 3, kc = q & 7;
    const __nv_bfloat16* xh = g_xhi + (size_t)m0 * DDIM;
    const __nv_bfloat16* xl = g_xlo + (size_t)m0 * DDIM;
    const __nv_bfloat16* eh = g_ehi + (size_t)(ph * 128) * DDIM;
    const __nv_bfloat16* el = g_elo + (size_t)(ph * 128) * DDIM;
    #pragma unroll
    for (int it = 0; it < 2; it++) {
        int idx = tid + it * 256;          // 0..511
        int row = idx >> 2, c16 = idx & 3;
        int gof = row * DDIM + kc * 32 + c16 * 8;
        uint32_t so = (uint32_t)(row * ROWB + c16 * 16);
        cpasync16(base + 0 * MATB + so, xh + gof);
        cpasync16(base + 1 * MATB + so, xl + gof);
        cpasync16(base + 2 * MATB + so, eh + gof);
        cpasync16(base + 3 * MATB + so, el + gof);
    }
}

__global__ void __launch_bounds__(256, 2) k_gemm() {
    extern __shared__ char dsm[];
    __shared__ float s_mb[2][128];
    __shared__ float s_ms[2][128];
    __shared__ int   s_mi[2][128];
    __shared__ int   s_msi[2][128];

    const uint32_t smb = smem_u32(dsm);
    float* c2s = (float*)(dsm + C2OFF);

    const int tid = threadIdx.x;
    const int wid = tid >> 5;
    const int lane = tid & 31;
    const int wm = wid >> 1;       // 0..3 (M)
    const int wn = wid & 1;        // 0..1 (N)
    const int m0 = blockIdx.x * 128;

    for (int i = tid; i < KK; i += 256) c2s[i] = g_c2[i];

    const int a_row = lane & 15;
    const int a_c8  = (lane >> 4) * 8;
    // B paired-x4 addressing: lanes 0-15 -> nt, lanes 16-31 -> nt+1
    const int b_row4   = lane & 7;
    const int b_c84    = ((lane >> 3) & 1) * 8;
    const int b_ntoff  = lane >> 4;            // 0 or 1

    float best[4] = {1e30f, 1e30f, 1e30f, 1e30f};
    float sec[4]  = {1e30f, 1e30f, 1e30f, 1e30f};
    int   bidx[4] = {0, 0, 0, 0};
    int   sidx[4] = {0, 0, 0, 0};

    issue_chunk(0, smb, tid, m0);
    CP_COMMIT();
    int buf = 0;

    for (int ph = 0; ph < 8; ph++) {
        float acc[2][8][4];
        #pragma unroll
        for (int mt = 0; mt < 2; mt++)
            #pragma unroll
            for (int nt = 0; nt < 8; nt++)
                #pragma unroll
                for (int r = 0; r < 4; r++) acc[mt][nt][r] = 0.f;

        for (int kc = 0; kc < 8; kc++) {
            CP_WAIT0();
            __syncthreads();   // single barrier: buf ready for all + prev buf free
            int q = ph * 8 + kc;
            if (q < 63) {
                issue_chunk(q + 1, smb + (uint32_t)((buf ^ 1) * BUFB), tid, m0);
                CP_COMMIT();
            }

            const uint32_t ab  = smb + (uint32_t)(buf * BUFB);
            const uint32_t alb = ab + MATB;
            const uint32_t bb  = ab + 2 * MATB;
            const uint32_t blb = ab + 3 * MATB;

            #pragma unroll
            for (int ks = 0; ks < 2; ks++) {
                const int kb = ks * 16;
                uint32_t ao0 = (uint32_t)((wm * 32 + a_row) * ROWB + (kb + a_c8) * 2);
                uint32_t ao1 = (uint32_t)((wm * 32 + 16 + a_row) * ROWB + (kb + a_c8) * 2);
                uint32_t ah0[4], ah1[4], al0[4], al1[4];
                ldm_x4(ab + ao0,  ah0[0], ah0[1], ah0[2], ah0[3]);
                ldm_x4(ab + ao1,  ah1[0], ah1[1], ah1[2], ah1[3]);
                ldm_x4(alb + ao0, al0[0], al0[1], al0[2], al0[3]);
                ldm_x4(alb + ao1, al1[0], al1[1], al1[2], al1[3]);

                #pragma unroll
                for (int half = 0; half < 2; half++) {
                    // B fragments for 4 nt via paired ldmatrix.x4 (2 nt per op)
                    uint32_t bh[4][2], bl[4][2];
                    #pragma unroll
                    for (int jj = 0; jj < 2; jj++) {
                        int ntp = half * 4 + jj * 2;   // nt pair base
                        uint32_t bo = (uint32_t)((wn * 64 + (ntp + b_ntoff) * 8 + b_row4) * ROWB
                                                 + (kb + b_c84) * 2);
                        ldm_x4(bb + bo,  bh[jj*2][0], bh[jj*2][1], bh[jj*2+1][0], bh[jj*2+1][1]);
                        ldm_x4(blb + bo, bl[jj*2][0], bl[jj*2][1], bl[jj*2+1][0], bl[jj*2+1][1]);
                    }
                    #pragma unroll
                    for (int j = 0; j < 4; j++) {
                        int nt = half * 4 + j;
                        mma_bf16(acc[0][nt], ah0, bh[j][0], bh[j][1]);
                        mma_bf16(acc[1][nt], ah1, bh[j][0], bh[j][1]);
                    }
                    #pragma unroll
                    for (int j = 0; j < 4; j++) {
                        int nt = half * 4 + j;
                        mma_bf16(acc[0][nt], al0, bh[j][0], bh[j][1]);
                        mma_bf16(acc[1][nt], al1, bh[j][0], bh[j][1]);
                    }
                    #pragma unroll
                    for (int j = 0; j < 4; j++) {
                        int nt = half * 4 + j;
                        mma_bf16(acc[0][nt], ah0, bl[j][0], bl[j][1]);
                        mma_bf16(acc[1][nt], ah1, bl[j][0], bl[j][1]);
                    }
                }
            }
            buf ^= 1;
        }

        // epilogue: scores + top-2 update (rows: wm*32 + mt*16 + h*8 + lane/4)
        #pragma unroll
        for (int mt = 0; mt < 2; mt++) {
            #pragma unroll
            for (int h = 0; h < 2; h++) {
                const int slot = mt * 2 + h;
                #pragma unroll
                for (int nt = 0; nt < 8; nt++) {
                    int k0 = ph * 128 + wn * 64 + nt * 8 + (lane & 3) * 2;
                    float s0 = fmaf(-2.f, acc[mt][nt][2 * h + 0], c2s[k0]);
                    float s1 = fmaf(-2.f, acc[mt][nt][2 * h + 1], c2s[k0 + 1]);
                    if (s0 < best[slot]) {
                        sec[slot] = best[slot]; sidx[slot] = bidx[slot];
                        best[slot] = s0; bidx[slot] = k0;
                    } else if (s0 < sec[slot]) { sec[slot] = s0; sidx[slot] = k0; }
                    if (s1 < best[slot]) {
                        sec[slot] = best[slot]; sidx[slot] = bidx[slot];
                        best[slot] = s1; bidx[slot] = k0 + 1;
                    } else if (s1 < sec[slot]) { sec[slot] = s1; sidx[slot] = k0 + 1; }
                }
            }
        }
    }

    // merge: quad shfl (4 lanes share a row), then the 2 N-warps via smem
    #pragma unroll
    for (int slot = 0; slot < 4; slot++) {
        float b = best[slot], s = sec[slot];
        int i = bidx[slot], si = sidx[slot];
        #pragma unroll
        for (int off = 1; off <= 2; off <<= 1) {
            float ob  = __shfl_xor_sync(0xffffffffu, b, off);
            float os  = __shfl_xor_sync(0xffffffffu, s, off);
            int   oi  = __shfl_xor_sync(0xffffffffu, i, off);
            int   osi = __shfl_xor_sync(0xffffffffu, si, off);
            merge_top2(b, i, s, si, ob, oi, os, osi);
        }
        if ((lane & 3) == 0) {
            int mt = slot >> 1, h = slot & 1;
            int row = wm * 32 + mt * 16 + h * 8 + (lane >> 2);
            s_mb[wn][row] = b; s_ms[wn][row] = s;
            s_mi[wn][row] = i; s_msi[wn][row] = si;
        }
    }
    __syncthreads();
    if (tid < 128) {
        float b = s_mb[0][tid], s = s_ms[0][tid];
        int i = s_mi[0][tid], si = s_msi[0][tid];
        merge_top2(b, i, s, si, s_mb[1][tid], s_mi[1][tid], s_ms[1][tid], s_msi[1][tid]);
        int n = m0 + tid;
        g_enc[n] = i;
        if (s - b < DELTA_TC) {
            g_sidx[n] = si;
            int pos = atomicAdd(&g_nflag, 1);
            g_flags[pos] = n;
        }
    }
}

// ---------------- Pass B: exact fp64 top-2 compare, one warp per point ----------------
__global__ __launch_bounds__(256) void k_passB(const float* __restrict__ x,
                                               const float* __restrict__ emb) {
    const int nf = g_nflag;
    const int gw = (blockIdx.x * blockDim.x + threadIdx.x) >> 5;
    const int nw = (gridDim.x * blockDim.x) >> 5;
    const int lane = threadIdx.x & 31;

    for (int fi = gw; fi < nf; fi += nw) {
        int n = g_flags[fi];
        int i1 = g_enc[n], i2 = g_sidx[n];
        int b = n / TT, t = n % TT;
        const float* xb = x + (size_t)b * DDIM * TT + t;
        double a1 = 0.0, a2 = 0.0;
        #pragma unroll
        for (int j = 0; j < 8; j++) {
            int d = lane * 8 + j;
            double xv = (double)xb[(size_t)d * TT];
            double e1 = (double)emb[i1 * DDIM + d];
            double e2 = (double)emb[i2 * DDIM + d];
            double f1 = xv - e1, f2 = xv - e2;
            a1 = fma(f1, f1, a1);
            a2 = fma(f2, f2, a2);
        }
        #pragma unroll
        for (int off = 16; off > 0; off >>= 1) {
            a1 += __shfl_down_sync(0xffffffffu, a1, off);
            a2 += __shfl_down_sync(0xffffffffu, a2, off);
        }
        if (lane == 0) {
            if (a2 < a1 || (a2 == a1 && i2 < i1)) g_enc[n] = i2;
        }
    }
}

// ---------------- quantized_st + MSE partials ----------------
__global__ __launch_bounds__(256) void k_quant(const float* __restrict__ x,
                                               const float* __restrict__ emb,
                                               float* __restrict__ out,
                                               int do_store) {
    __shared__ float sf[256];
    const int tid = threadIdx.x;
    const int gi = blockIdx.x * 256 + tid;
    const size_t base = (size_t)gi * 4;

    int t = (int)(base % TT);
    size_t tmp = base / TT;
    int d = (int)(tmp % DDIM);
    int b = (int)(tmp / DDIM);

    float4 xv = *(const float4*)&x[base];
    int nb = b * TT + t;
    int i0 = g_enc[nb + 0];
    int i1 = g_enc[nb + 1];
    int i2 = g_enc[nb + 2];
    int i3 = g_enc[nb + 3];
    float q0 = __ldg(&emb[i0 * DDIM + d]);
    float q1 = __ldg(&emb[i1 * DDIM + d]);
    float q2 = __ldg(&emb[i2 * DDIM + d]);
    float q3 = __ldg(&emb[i3 * DDIM + d]);
    float d0 = q0 - xv.x;
    float d1 = q1 - xv.y;
    float d2 = q2 - xv.z;
    float d3 = q3 - xv.w;
    if (do_store) {
        float4 ov = make_float4(xv.x + d0, xv.y + d1, xv.z + d2, xv.w + d3);
        *(float4*)&out[base] = ov;
    }
    float loc = d0 * d0;
    loc = fmaf(d1, d1, loc);
    loc = fmaf(d2, d2, loc);
    loc = fmaf(d3, d3, loc);

    sf[tid] = loc;
    __syncthreads();
    for (int off = 128; off > 0; off >>= 1) {
        if (tid < off) sf[tid] += sf[tid + off];
        __syncthreads();
    }
    if (tid == 0) g_bsum[blockIdx.x] = (double)sf[0];
}

// Block 0: deterministic final MSE reduce + scalars. Blocks 1..128: indices.
__global__ void k_finish(float* __restrict__ out, int out_size) {
    if (blockIdx.x == 0) {
        __shared__ double sd[256];
        const int tid = threadIdx.x;
        double loc = 0.0;
        for (int i = tid; i < 8192; i += 256) loc += g_bsum[i];
        sd[tid] = loc;
        __syncthreads();
        for (int off = 128; off > 0; off >>= 1) {
            if (tid < off) sd[tid] += sd[tid + off];
            __syncthreads();
        }
        if (tid == 0 && out_size >= NQ + 3) {
            float mse = (float)(sd[0] / (double)NQ);
            out[NQ + 0] = mse + 0.25f * mse;
            out[NQ + 1] = mse;
            out[NQ + 2] = mse;
        }
    } else {
        int i = (blockIdx.x - 1) * 256 + threadIdx.x;
        if (i < NPTS && out_size >= NQ + 3 + NPTS)
            out[NQ + 3 + i] = (float)g_enc[i];
    }
}

extern "C" void kernel_launch(void* const* d_in, const int* in_sizes, int n_in,
                              void* d_out, int out_size) {
    const float* x   = (const float*)d_in[0];
    const float* emb = (const float*)d_in[1];
    if (n_in >= 2 && in_sizes[0] == KK * DDIM && in_sizes[1] == NQ) {
        const float* tmp = x; x = emb; emb = tmp;
    }
    float* out = (float*)d_out;
    int do_store = (out_size >= NQ) ? 1 : 0;

    static int attr_set = 0;
    if (!attr_set) {
        cudaFuncSetAttribute(k_gemm, cudaFuncAttributeMaxDynamicSharedMemorySize, GEMM_DSMEM);
        attr_set = 1;
    }

    k_prep_e<<<KK, 256>>>(emb);
    k_prep_x<<<dim3(TT / 32, DDIM / 32, BN), dim3(32, 8)>>>(x);
    k_gemm<<<NPTS / 128, 256, GEMM_DSMEM>>>();
    k_passB<<<128, 256>>>(x, emb);
    k_quant<<<NQ / (256 * 4), 256>>>(x, emb, out, do_store);
    k_finish<<<1 + NPTS / 256, 256>>>(out, out_size);
}